// round 1
// baseline (speedup 1.0000x reference)
#include <cuda_runtime.h>

// Problem constants (fixed shapes)
#define BB 4
#define SS 1024
#define DD 1024
#define HH 16
#define DKC 64
#define DFF 4096

// ---------------- scratch (static device globals; no allocation) -------------
__device__ float g_q [BB*HH*SS*DKC];          // 16 MB  [b,h,s,k]
__device__ float g_k [BB*HH*SS*DKC];          // 16 MB
__device__ float g_v [BB*HH*SS*DKC];          // 16 MB
__device__ float g_sc[67108864];              // 256 MB [b,h,s,t] scores
__device__ float g_oc[BB*SS*HH*DKC];          // 16 MB  [b,s,h*64+k]
__device__ float g_at[BB*SS*DD];              // 16 MB
__device__ float g_x1[BB*SS*DD];              // 16 MB
__device__ float g_ff[BB*SS*DFF];             // 64 MB
__device__ float g_ps[BB*SS*DD];              // 16 MB

// ---------------- helpers ----------------------------------------------------
__device__ __forceinline__ unsigned f2tf(float x) {
    unsigned u;
    asm("cvt.rna.tf32.f32 %0, %1;" : "=r"(u) : "f"(x));
    return u;
}

// swizzled k-major smem index: tile is [32 k][128 mn]
// f(k) = ((k&3)<<3) ^ (((k>>2)&7)<<2) -> conflict-free for writers and readers
__device__ __forceinline__ int swz(int k, int x) {
    return k * 128 + (x ^ (((k & 3) << 3) ^ (((k >> 2) & 7) << 2)));
}

__device__ __forceinline__ void mma8(float* c, const unsigned* a, const unsigned* b) {
    asm volatile(
        "mma.sync.aligned.m16n8k8.row.col.f32.tf32.tf32.f32 "
        "{%0,%1,%2,%3},{%4,%5,%6,%7},{%8,%9},{%0,%1,%2,%3};"
        : "+f"(c[0]), "+f"(c[1]), "+f"(c[2]), "+f"(c[3])
        : "r"(a[0]), "r"(a[1]), "r"(a[2]), "r"(a[3]), "r"(b[0]), "r"(b[1]));
}

// ---------------- generic TF32 GEMM ------------------------------------------
// C = epi( A @ B' )   A: [M,K] row-major fp32
// OPB: 0 = B [K,N] row-major; 1 = B [N,K] row-major (C = A@B^T); 2 = QKV weight
//      gather (B[d][n] = W[n>>6][d][n&63], W is [H,D,DK])
// EPI: 0 = plain C[z*Cz + m*N + n]; 1 = QKV scatter to [b,h,s,k] (v=(acc+bias)*alpha);
//      2 = AV scatter to concat [b,s,h*64+k]
template<int OPB, int EPI>
__global__ void __launch_bounds__(256)
gemm_tf32(const float* __restrict__ A, const float* __restrict__ Bm,
          const float* __restrict__ bias, float* __restrict__ C,
          int M, int N, int K, float alpha, int relu,
          long long Az, long long Bz, long long Cz)
{
    __shared__ unsigned As[32 * 128];
    __shared__ unsigned Bs[32 * 128];

    const int tid  = threadIdx.x;
    const int lane = tid & 31;
    const int wid  = tid >> 5;
    const int wm   = wid & 1;        // warp tile 64(M) x 32(N); warps 2x4
    const int wn   = wid >> 1;
    const int z    = blockIdx.z;
    const float* Ag = A + (long long)z * Az;
    const float* Bg = Bm + (long long)z * Bz;

    const int Rb = blockIdx.y * 128;
    const int Nb = blockIdx.x * 128;

    float acc[4][4][4];
#pragma unroll
    for (int i = 0; i < 4; i++)
#pragma unroll
        for (int j = 0; j < 4; j++)
#pragma unroll
            for (int r = 0; r < 4; r++) acc[i][j][r] = 0.f;

    const int tq = lane & 3;   // thread-in-group
    const int gq = lane >> 2;  // group id

    for (int k0 = 0; k0 < K; k0 += 32) {
        // ---- stage A tile (128 rows x 32 k), transposed+swizzled ----
        {
            const int row = tid >> 3;          // 0..31
            const int c4  = (tid & 7) * 4;     // 0..28
#pragma unroll
            for (int i = 0; i < 4; i++) {
                const int r = row + 32 * i;
                float4 v = *(const float4*)(Ag + (long long)(Rb + r) * K + k0 + c4);
                As[swz(c4 + 0, r)] = f2tf(v.x);
                As[swz(c4 + 1, r)] = f2tf(v.y);
                As[swz(c4 + 2, r)] = f2tf(v.z);
                As[swz(c4 + 3, r)] = f2tf(v.w);
            }
        }
        // ---- stage B tile (32 k x 128 n) ----
        if (OPB == 0 || OPB == 2) {
            const int kr = tid >> 5;           // 0..7
            const int nc = (tid & 31) * 4;     // 0..124
#pragma unroll
            for (int i = 0; i < 4; i++) {
                const int kk = kr + 8 * i;
                const int gn = Nb + nc;
                float4 v;
                if (gn < N) {
                    if (OPB == 0) {
                        v = *(const float4*)(Bg + (long long)(k0 + kk) * N + gn);
                    } else {
                        const int h = gn >> 6;
                        v = *(const float4*)(Bg + ((long long)h * K + (k0 + kk)) * 64 + (gn & 63));
                    }
                } else {
                    v = make_float4(0.f, 0.f, 0.f, 0.f);
                }
                uint4 u;
                u.x = f2tf(v.x); u.y = f2tf(v.y); u.z = f2tf(v.z); u.w = f2tf(v.w);
                *(uint4*)&Bs[swz(kk, nc)] = u;
            }
        } else { // OPB == 1 : B is [N,K] row-major -> Bs[k][n] = B[n][k]
            const int nr = tid >> 3;           // 0..31
            const int c4 = (tid & 7) * 4;      // 0..28
#pragma unroll
            for (int i = 0; i < 4; i++) {
                const int nn = nr + 32 * i;
                const int gn = Nb + nn;
                float4 v;
                if (gn < N) v = *(const float4*)(Bg + (long long)gn * K + k0 + c4);
                else        v = make_float4(0.f, 0.f, 0.f, 0.f);
                Bs[swz(c4 + 0, nn)] = f2tf(v.x);
                Bs[swz(c4 + 1, nn)] = f2tf(v.y);
                Bs[swz(c4 + 2, nn)] = f2tf(v.z);
                Bs[swz(c4 + 3, nn)] = f2tf(v.w);
            }
        }
        __syncthreads();

        // ---- compute: 4 k8-steps, 4x4 m16n8 tiles per warp ----
#pragma unroll
        for (int k8 = 0; k8 < 4; k8++) {
            const int clo = k8 * 8 + tq;
            const int chi = clo + 4;
            unsigned af[4][4], bf[4][2];
#pragma unroll
            for (int mt = 0; mt < 4; mt++) {
                const int r = wm * 64 + mt * 16 + gq;
                af[mt][0] = As[swz(clo, r)];
                af[mt][1] = As[swz(clo, r + 8)];
                af[mt][2] = As[swz(chi, r)];
                af[mt][3] = As[swz(chi, r + 8)];
            }
#pragma unroll
            for (int nt = 0; nt < 4; nt++) {
                const int n = wn * 32 + nt * 8 + gq;
                bf[nt][0] = Bs[swz(clo, n)];
                bf[nt][1] = Bs[swz(chi, n)];
            }
#pragma unroll
            for (int mt = 0; mt < 4; mt++)
#pragma unroll
                for (int nt = 0; nt < 4; nt++)
                    mma8(acc[mt][nt], af[mt], bf[nt]);
        }
        __syncthreads();
    }

    // ---- epilogue ----
    const int qr = gq;
    const int qc = tq * 2;
#pragma unroll
    for (int mt = 0; mt < 4; mt++) {
#pragma unroll
        for (int nt = 0; nt < 4; nt++) {
            const int m0 = Rb + wm * 64 + mt * 16 + qr;
            const int n0 = Nb + wn * 32 + nt * 8 + qc;
#pragma unroll
            for (int e = 0; e < 4; e++) {
                const int m = m0 + (e >> 1) * 8;
                const int n = n0 + (e & 1);
                if (n >= N) continue;
                float v = acc[mt][nt][e];
                if (bias) v += bias[n];
                v *= alpha;
                if (relu) v = fmaxf(v, 0.f);
                long long oi;
                if (EPI == 0) {
                    oi = (long long)z * Cz + (long long)m * N + n;
                } else if (EPI == 1) { // QKV: m=(b,s) n=(h,k) -> [b,h,s,k]
                    const int b = m >> 10, s = m & 1023;
                    const int h = n >> 6,  kk = n & 63;
                    oi = ((long long)((b * HH + h) * SS + s)) * DKC + kk;
                } else {               // AV: z=(b,h), m=s, n=k -> [b,s,h*64+k]
                    const int b = z >> 4, h = z & 15;
                    oi = ((long long)(b * SS + m)) * DD + h * DKC + n;
                }
                C[oi] = v;
            }
        }
    }
}

// ---------------- softmax over rows of 1024 ----------------------------------
__global__ void __launch_bounds__(256) softmax_kernel(float* __restrict__ sc)
{
    __shared__ float red[8];
    const long long base = (long long)blockIdx.x * 1024;
    const int tid = threadIdx.x;
    float4 v = *(float4*)(sc + base + tid * 4);

    float m = fmaxf(fmaxf(v.x, v.y), fmaxf(v.z, v.w));
#pragma unroll
    for (int o = 16; o; o >>= 1) m = fmaxf(m, __shfl_xor_sync(0xffffffffu, m, o));
    if ((tid & 31) == 0) red[tid >> 5] = m;
    __syncthreads();
    if (tid < 32) {
        float mm = (tid < 8) ? red[tid] : -3.402823466e38f;
#pragma unroll
        for (int o = 4; o; o >>= 1) mm = fmaxf(mm, __shfl_xor_sync(0xffffffffu, mm, o));
        if (tid == 0) red[0] = mm;
    }
    __syncthreads();
    m = red[0];

    v.x = expf(v.x - m); v.y = expf(v.y - m);
    v.z = expf(v.z - m); v.w = expf(v.w - m);
    float s = v.x + v.y + v.z + v.w;
    __syncthreads();  // protect red[] reuse
#pragma unroll
    for (int o = 16; o; o >>= 1) s += __shfl_xor_sync(0xffffffffu, s, o);
    if ((tid & 31) == 0) red[tid >> 5] = s;
    __syncthreads();
    if (tid < 32) {
        float ss = (tid < 8) ? red[tid] : 0.f;
#pragma unroll
        for (int o = 4; o; o >>= 1) ss += __shfl_xor_sync(0xffffffffu, ss, o);
        if (tid == 0) red[0] = ss;
    }
    __syncthreads();
    const float inv = 1.f / red[0];
    v.x *= inv; v.y *= inv; v.z *= inv; v.w *= inv;
    *(float4*)(sc + base + tid * 4) = v;
}

// ---------------- out = x + LayerNorm(t)*g + b (row = 1024) -------------------
__global__ void __launch_bounds__(256)
add_ln_kernel(const float* __restrict__ x, const float* __restrict__ t,
              const float* __restrict__ gw, const float* __restrict__ bw,
              float* __restrict__ out)
{
    __shared__ float r1[8], r2[8];
    const long long base = (long long)blockIdx.x * 1024;
    const int tid = threadIdx.x;
    float4 tv = *(const float4*)(t + base + tid * 4);
    float s = tv.x + tv.y + tv.z + tv.w;
    float q = tv.x * tv.x + tv.y * tv.y + tv.z * tv.z + tv.w * tv.w;
#pragma unroll
    for (int o = 16; o; o >>= 1) {
        s += __shfl_xor_sync(0xffffffffu, s, o);
        q += __shfl_xor_sync(0xffffffffu, q, o);
    }
    if ((tid & 31) == 0) { r1[tid >> 5] = s; r2[tid >> 5] = q; }
    __syncthreads();
    if (tid < 32) {
        float ss = (tid < 8) ? r1[tid] : 0.f;
        float qq = (tid < 8) ? r2[tid] : 0.f;
#pragma unroll
        for (int o = 4; o; o >>= 1) {
            ss += __shfl_xor_sync(0xffffffffu, ss, o);
            qq += __shfl_xor_sync(0xffffffffu, qq, o);
        }
        if (tid == 0) { r1[0] = ss; r2[0] = qq; }
    }
    __syncthreads();
    const float mean = r1[0] * (1.f / 1024.f);
    const float var  = r2[0] * (1.f / 1024.f) - mean * mean;
    const float rstd = rsqrtf(var + 1e-5f);

    float4 xv = *(const float4*)(x + base + tid * 4);
    float4 gv = *(const float4*)(gw + tid * 4);
    float4 bv = *(const float4*)(bw + tid * 4);
    float4 o;
    o.x = xv.x + (tv.x - mean) * rstd * gv.x + bv.x;
    o.y = xv.y + (tv.y - mean) * rstd * gv.y + bv.y;
    o.z = xv.z + (tv.z - mean) * rstd * gv.z + bv.z;
    o.w = xv.w + (tv.w - mean) * rstd * gv.w + bv.w;
    *(float4*)(out + base + tid * 4) = o;
}

// ---------------- launch ------------------------------------------------------
static float* sym_addr(const void* s) {
    void* p = nullptr;
    cudaGetSymbolAddress(&p, s);
    return (float*)p;
}

extern "C" void kernel_launch(void* const* d_in, const int* in_sizes, int n_in,
                              void* d_out, int out_size)
{
    (void)in_sizes; (void)n_in; (void)out_size;
    const float* x   = (const float*)d_in[0];
    const float* Wq  = (const float*)d_in[1];
    const float* bq  = (const float*)d_in[2];
    const float* Wk  = (const float*)d_in[3];
    const float* bk  = (const float*)d_in[4];
    const float* Wv  = (const float*)d_in[5];
    const float* bv  = (const float*)d_in[6];
    const float* Wo  = (const float*)d_in[7];
    const float* bo  = (const float*)d_in[8];
    const float* W1  = (const float*)d_in[9];
    const float* b1  = (const float*)d_in[10];
    const float* W2  = (const float*)d_in[11];
    const float* b2  = (const float*)d_in[12];
    const float* g1  = (const float*)d_in[13];
    const float* be1 = (const float*)d_in[14];
    const float* g2  = (const float*)d_in[15];
    const float* be2 = (const float*)d_in[16];
    float* out = (float*)d_out;

    float* q  = sym_addr(g_q);
    float* k  = sym_addr(g_k);
    float* v  = sym_addr(g_v);
    float* sc = sym_addr(g_sc);
    float* oc = sym_addr(g_oc);
    float* at = sym_addr(g_at);
    float* x1 = sym_addr(g_x1);
    float* ff = sym_addr(g_ff);
    float* ps = sym_addr(g_ps);

    const dim3 blk(256);
    const float rs = 0.125f;  // 1/sqrt(DK)

    // QKV projections: [4096,1024] @ [1024,1024] with head-gather, scatter to [b,h,s,k]
    gemm_tf32<2, 1><<<dim3(8, 32, 1), blk>>>(x, Wq, bq, q, 4096, 1024, 1024, rs,  0, 0, 0, 0);
    gemm_tf32<2, 1><<<dim3(8, 32, 1), blk>>>(x, Wk, bk, k, 4096, 1024, 1024, 1.f, 0, 0, 0, 0);
    gemm_tf32<2, 1><<<dim3(8, 32, 1), blk>>>(x, Wv, bv, v, 4096, 1024, 1024, 1.f, 0, 0, 0, 0);

    // scores[z] = q[z] @ k[z]^T  (z = b*H+h, 64 batches), scale already in q
    gemm_tf32<1, 0><<<dim3(8, 8, 64), blk>>>(q, k, nullptr, sc, 1024, 1024, 64, 1.f, 0,
                                             65536LL, 65536LL, 1048576LL);
    softmax_kernel<<<65536, blk>>>(sc);

    // o[z] = attn[z] @ v[z], scattered to concat layout [b,s,h*64+k]
    gemm_tf32<0, 2><<<dim3(1, 8, 64), blk>>>(sc, v, nullptr, oc, 1024, 64, 1024, 1.f, 0,
                                             1048576LL, 65536LL, 0LL);

    // output projection
    gemm_tf32<0, 0><<<dim3(8, 32, 1), blk>>>(oc, Wo, bo, at, 4096, 1024, 1024, 1.f, 0, 0, 0, 0);
    // x1 = x + LN(att)
    add_ln_kernel<<<4096, blk>>>(x, at, g1, be1, x1);

    // FFN
    gemm_tf32<0, 0><<<dim3(32, 32, 1), blk>>>(x1, W1, b1, ff, 4096, 4096, 1024, 1.f, 1, 0, 0, 0);
    gemm_tf32<0, 0><<<dim3(8, 32, 1), blk>>>(ff, W2, b2, ps, 4096, 1024, 4096, 1.f, 0, 0, 0, 0);

    // out = x1 + LN(pos)
    add_ln_kernel<<<4096, blk>>>(x1, ps, g2, be2, out);
}

// round 2
// speedup vs baseline: 1.4738x; 1.4738x over previous
#include <cuda_runtime.h>

#define BB 4
#define SS 1024
#define DD 1024
#define HH 16
#define DKC 64
#define DFF 4096

// ---------------- scratch ----------------
__device__ float g_q [BB*HH*SS*DKC];
__device__ float g_k [BB*HH*SS*DKC];
__device__ float g_v [BB*HH*SS*DKC];
__device__ float g_oc[BB*SS*HH*DKC];
__device__ float g_at[BB*SS*DD];
__device__ float g_x1[BB*SS*DD];
__device__ float g_ff[BB*SS*DFF];
__device__ float g_ps[BB*SS*DD];

// ---------------- helpers ----------------
__device__ __forceinline__ unsigned f2tf(float x) {
    unsigned u;
    asm("cvt.rna.tf32.f32 %0, %1;" : "=r"(u) : "f"(x));
    return u;
}

// swizzled k-major smem index for dense GEMM tiles [32 k][128 mn]
__device__ __forceinline__ int swz(int k, int x) {
    return k * 128 + (x ^ (((k & 3) << 3) ^ (((k >> 2) & 7) << 2)));
}

__device__ __forceinline__ void mma8(float* c, const unsigned* a, const unsigned* b) {
    asm volatile(
        "mma.sync.aligned.m16n8k8.row.col.f32.tf32.tf32.f32 "
        "{%0,%1,%2,%3},{%4,%5,%6,%7},{%8,%9},{%0,%1,%2,%3};"
        : "+f"(c[0]), "+f"(c[1]), "+f"(c[2]), "+f"(c[3])
        : "r"(a[0]), "r"(a[1]), "r"(a[2]), "r"(a[3]), "r"(b[0]), "r"(b[1]));
}

// ---------------- dense TF32 GEMM, double-buffered ----------------
// OPB: 0 = B [K,N] row-major; 2 = QKV weight gather (W is [H,D,DK])
// EPI: 0 = C[m*N+n]; 1 = QKV scatter to [b,h,s,k] with v=(acc+bias)*alpha
template<int OPB, int EPI>
__global__ void __launch_bounds__(256)
gemm_tf32(const float* __restrict__ A, const float* __restrict__ Bm,
          const float* __restrict__ bias, float* __restrict__ C,
          int M, int N, int K, float alpha, int relu)
{
    extern __shared__ unsigned dsm[];
    unsigned* As = dsm;          // 2 x 4096
    unsigned* Bs = dsm + 8192;   // 2 x 4096

    const int tid  = threadIdx.x;
    const int lane = tid & 31;
    const int wid  = tid >> 5;
    const int wm   = wid & 1;
    const int wn   = wid >> 1;
    const int Rb = blockIdx.y * 128;
    const int Nb = blockIdx.x * 128;

    const int arow = tid >> 3, ac4 = (tid & 7) * 4;
    const int bkr  = tid >> 5, bnc = (tid & 31) * 4;
    const int tq = lane & 3, gq = lane >> 2;

    float4 ra[4], rb[4];

    auto ldA = [&](int k0) {
#pragma unroll
        for (int i = 0; i < 4; i++)
            ra[i] = *(const float4*)(A + (Rb + arow + 32 * i) * K + k0 + ac4);
    };
    auto ldB = [&](int k0) {
#pragma unroll
        for (int i = 0; i < 4; i++) {
            const int kk = k0 + bkr + 8 * i;
            const int gn = Nb + bnc;
            if (OPB == 0)
                rb[i] = *(const float4*)(Bm + kk * N + gn);
            else
                rb[i] = *(const float4*)(Bm + ((gn >> 6) * K + kk) * 64 + (gn & 63));
        }
    };
    auto stA = [&](int buf) {
        unsigned* d = As + buf * 4096;
#pragma unroll
        for (int i = 0; i < 4; i++) {
            const int r = arow + 32 * i;
            d[swz(ac4 + 0, r)] = f2tf(ra[i].x);
            d[swz(ac4 + 1, r)] = f2tf(ra[i].y);
            d[swz(ac4 + 2, r)] = f2tf(ra[i].z);
            d[swz(ac4 + 3, r)] = f2tf(ra[i].w);
        }
    };
    auto stB = [&](int buf) {
        unsigned* d = Bs + buf * 4096;
#pragma unroll
        for (int i = 0; i < 4; i++) {
            uint4 u;
            u.x = f2tf(rb[i].x); u.y = f2tf(rb[i].y);
            u.z = f2tf(rb[i].z); u.w = f2tf(rb[i].w);
            *(uint4*)&d[swz(bkr + 8 * i, bnc)] = u;
        }
    };

    float acc[4][4][4];
#pragma unroll
    for (int i = 0; i < 4; i++)
#pragma unroll
        for (int j = 0; j < 4; j++)
#pragma unroll
            for (int r = 0; r < 4; r++) acc[i][j][r] = 0.f;

    ldA(0); ldB(0);
    stA(0); stB(0);
    __syncthreads();

    const int nK = K >> 5;
    for (int it = 0; it < nK; it++) {
        const int cur = it & 1;
        if (it + 1 < nK) { ldA((it + 1) << 5); ldB((it + 1) << 5); }

        const unsigned* Ab = As + cur * 4096;
        const unsigned* Bb = Bs + cur * 4096;
#pragma unroll
        for (int k8 = 0; k8 < 4; k8++) {
            const int clo = k8 * 8 + tq;
            const int chi = clo + 4;
            unsigned af[4][4], bf[4][2];
#pragma unroll
            for (int mt = 0; mt < 4; mt++) {
                const int r = wm * 64 + mt * 16 + gq;
                af[mt][0] = Ab[swz(clo, r)];
                af[mt][1] = Ab[swz(clo, r + 8)];
                af[mt][2] = Ab[swz(chi, r)];
                af[mt][3] = Ab[swz(chi, r + 8)];
            }
#pragma unroll
            for (int nt = 0; nt < 4; nt++) {
                const int n = wn * 32 + nt * 8 + gq;
                bf[nt][0] = Bb[swz(clo, n)];
                bf[nt][1] = Bb[swz(chi, n)];
            }
#pragma unroll
            for (int mt = 0; mt < 4; mt++)
#pragma unroll
                for (int nt = 0; nt < 4; nt++)
                    mma8(acc[mt][nt], af[mt], bf[nt]);
        }

        if (it + 1 < nK) { stA(cur ^ 1); stB(cur ^ 1); }
        __syncthreads();
    }

    // epilogue (float2 stores)
#pragma unroll
    for (int mt = 0; mt < 4; mt++) {
#pragma unroll
        for (int nt = 0; nt < 4; nt++) {
            const int m0 = Rb + wm * 64 + mt * 16 + gq;
            const int n0 = Nb + wn * 32 + nt * 8 + tq * 2;
#pragma unroll
            for (int half = 0; half < 2; half++) {
                const int m = m0 + half * 8;
                float v0 = acc[mt][nt][half * 2 + 0];
                float v1 = acc[mt][nt][half * 2 + 1];
                if (bias) { v0 += bias[n0]; v1 += bias[n0 + 1]; }
                v0 *= alpha; v1 *= alpha;
                if (relu) { v0 = fmaxf(v0, 0.f); v1 = fmaxf(v1, 0.f); }
                int oi;
                if (EPI == 0) {
                    oi = m * N + n0;
                } else {
                    const int b = m >> 10, s = m & 1023;
                    const int h = n0 >> 6, c = n0 & 63;
                    oi = ((b * HH + h) * SS + s) * DKC + c;
                }
                *(float2*)&C[oi] = make_float2(v0, v1);
            }
        }
    }
}

// ---------------- flash attention ----------------
// Q,K,V: [z=b*H+h][1024][64] fp32 (q pre-scaled).  O: [b,s,h*64+k] fp32.
// grid (8 q-tiles, 64 z), 256 threads; warp w owns output rows 16w..16w+15.
__global__ void __launch_bounds__(256)
flash_attn(const float* __restrict__ Qg, const float* __restrict__ Kg,
           const float* __restrict__ Vg, float* __restrict__ O)
{
    extern __shared__ unsigned sm[];
    unsigned* sQ  = sm;                 // [128][68]
    unsigned* sK  = sQ + 128 * 68;      // [128][68]
    unsigned* sVT = sK + 128 * 68;      // [64][132]  (V transposed: dk x key)
    unsigned* sP  = sVT + 64 * 132;     // 8 warps x [16][132]

    const int tid = threadIdx.x, lane = tid & 31, wid = tid >> 5;
    const int tq = lane & 3, gq = lane >> 2;
    const int z = blockIdx.y, qt = blockIdx.x;
    const float* Qp = Qg + (z * 1024 + qt * 128) * 64;
    const float* Kp = Kg + z * 1024 * 64;
    const float* Vp = Vg + z * 1024 * 64;

    // stage Q tile (tf32, stride 68 -> conflict-free fragment reads)
    for (int i = tid; i < 2048; i += 256) {
        const int r = i >> 4, c = (i & 15) << 2;
        float4 v = *(const float4*)(Qp + r * 64 + c);
        unsigned* d = sQ + r * 68 + c;
        d[0] = f2tf(v.x); d[1] = f2tf(v.y); d[2] = f2tf(v.z); d[3] = f2tf(v.w);
    }

    float oacc[8][4];
#pragma unroll
    for (int i = 0; i < 8; i++)
#pragma unroll
        for (int j = 0; j < 4; j++) oacc[i][j] = 0.f;
    float mrow0 = -1e30f, mrow1 = -1e30f, lrow0 = 0.f, lrow1 = 0.f;

    unsigned* sPw = sP + wid * 16 * 132;
    const int r0 = wid * 16 + gq;

    for (int kt = 0; kt < 8; kt++) {
        __syncthreads();    // prev iter's PV done before K/V overwrite
        // stage K and V tiles
        for (int i = tid; i < 2048; i += 256) {
            const int r = i >> 4, c = (i & 15) << 2;
            float4 kv = *(const float4*)(Kp + (kt * 128 + r) * 64 + c);
            unsigned* d = sK + r * 68 + c;
            d[0] = f2tf(kv.x); d[1] = f2tf(kv.y); d[2] = f2tf(kv.z); d[3] = f2tf(kv.w);
            float4 vv = *(const float4*)(Vp + (kt * 128 + r) * 64 + c);
            sVT[(c + 0) * 132 + r] = f2tf(vv.x);
            sVT[(c + 1) * 132 + r] = f2tf(vv.y);
            sVT[(c + 2) * 132 + r] = f2tf(vv.z);
            sVT[(c + 3) * 132 + r] = f2tf(vv.w);
        }
        __syncthreads();

        // S = Q @ K^T  (16 rows x 128 keys per warp)
        float sacc[16][4];
#pragma unroll
        for (int i = 0; i < 16; i++)
#pragma unroll
            for (int j = 0; j < 4; j++) sacc[i][j] = 0.f;
#pragma unroll
        for (int k8 = 0; k8 < 8; k8++) {
            const int clo = k8 * 8 + tq, chi = clo + 4;
            unsigned a[4];
            a[0] = sQ[r0 * 68 + clo];
            a[1] = sQ[(r0 + 8) * 68 + clo];
            a[2] = sQ[r0 * 68 + chi];
            a[3] = sQ[(r0 + 8) * 68 + chi];
#pragma unroll
            for (int nt = 0; nt < 16; nt++) {
                unsigned b[2];
                const int n = nt * 8 + gq;
                b[0] = sK[n * 68 + clo];
                b[1] = sK[n * 68 + chi];
                mma8(sacc[nt], a, b);
            }
        }

        // online softmax (rows r0 and r0+8; cols spread over the tq quad)
        float m0 = -1e30f, m1 = -1e30f;
#pragma unroll
        for (int nt = 0; nt < 16; nt++) {
            m0 = fmaxf(m0, fmaxf(sacc[nt][0], sacc[nt][1]));
            m1 = fmaxf(m1, fmaxf(sacc[nt][2], sacc[nt][3]));
        }
        m0 = fmaxf(m0, __shfl_xor_sync(0xffffffffu, m0, 1));
        m0 = fmaxf(m0, __shfl_xor_sync(0xffffffffu, m0, 2));
        m1 = fmaxf(m1, __shfl_xor_sync(0xffffffffu, m1, 1));
        m1 = fmaxf(m1, __shfl_xor_sync(0xffffffffu, m1, 2));
        const float mn0 = fmaxf(mrow0, m0), mn1 = fmaxf(mrow1, m1);
        const float sc0 = expf(mrow0 - mn0), sc1 = expf(mrow1 - mn1);

        float rs0 = 0.f, rs1 = 0.f;
#pragma unroll
        for (int nt = 0; nt < 16; nt++) {
            const float p0 = expf(sacc[nt][0] - mn0);
            const float p1 = expf(sacc[nt][1] - mn0);
            const float p2 = expf(sacc[nt][2] - mn1);
            const float p3 = expf(sacc[nt][3] - mn1);
            rs0 += p0 + p1; rs1 += p2 + p3;
            *(uint2*)&sPw[gq * 132 + nt * 8 + 2 * tq]       = make_uint2(f2tf(p0), f2tf(p1));
            *(uint2*)&sPw[(gq + 8) * 132 + nt * 8 + 2 * tq] = make_uint2(f2tf(p2), f2tf(p3));
        }
        rs0 += __shfl_xor_sync(0xffffffffu, rs0, 1);
        rs0 += __shfl_xor_sync(0xffffffffu, rs0, 2);
        rs1 += __shfl_xor_sync(0xffffffffu, rs1, 1);
        rs1 += __shfl_xor_sync(0xffffffffu, rs1, 2);
        lrow0 = lrow0 * sc0 + rs0;
        lrow1 = lrow1 * sc1 + rs1;
        mrow0 = mn0; mrow1 = mn1;
#pragma unroll
        for (int nt = 0; nt < 8; nt++) {
            oacc[nt][0] *= sc0; oacc[nt][1] *= sc0;
            oacc[nt][2] *= sc1; oacc[nt][3] *= sc1;
        }
        __syncwarp();

        // O += P @ V  (K dim = 128 keys)
#pragma unroll
        for (int k8 = 0; k8 < 16; k8++) {
            const int clo = k8 * 8 + tq, chi = clo + 4;
            unsigned a[4];
            a[0] = sPw[gq * 132 + clo];
            a[1] = sPw[(gq + 8) * 132 + clo];
            a[2] = sPw[gq * 132 + chi];
            a[3] = sPw[(gq + 8) * 132 + chi];
#pragma unroll
            for (int nt = 0; nt < 8; nt++) {
                unsigned b[2];
                const int n = nt * 8 + gq;
                b[0] = sVT[n * 132 + clo];
                b[1] = sVT[n * 132 + chi];
                mma8(oacc[nt], a, b);
            }
        }
    }

    // epilogue: normalize and scatter to concat layout [b,s,h*64+k]
    const float i0 = 1.f / lrow0, i1 = 1.f / lrow1;
    const int b = z >> 4, h = z & 15;
    const int s0 = qt * 128 + wid * 16 + gq;
#pragma unroll
    for (int nt = 0; nt < 8; nt++) {
        const int col = h * 64 + nt * 8 + 2 * tq;
        *(float2*)&O[(b * 1024 + s0) * 1024 + col] =
            make_float2(oacc[nt][0] * i0, oacc[nt][1] * i0);
        *(float2*)&O[(b * 1024 + s0 + 8) * 1024 + col] =
            make_float2(oacc[nt][2] * i1, oacc[nt][3] * i1);
    }
}

// ---------------- out = x + LayerNorm(t)*g + b ----------------
__global__ void __launch_bounds__(256)
add_ln_kernel(const float* __restrict__ x, const float* __restrict__ t,
              const float* __restrict__ gw, const float* __restrict__ bw,
              float* __restrict__ out)
{
    __shared__ float r1[8], r2[8];
    const int base = blockIdx.x * 1024;
    const int tid = threadIdx.x;
    float4 tv = *(const float4*)(t + base + tid * 4);
    float s = tv.x + tv.y + tv.z + tv.w;
    float q = tv.x * tv.x + tv.y * tv.y + tv.z * tv.z + tv.w * tv.w;
#pragma unroll
    for (int o = 16; o; o >>= 1) {
        s += __shfl_xor_sync(0xffffffffu, s, o);
        q += __shfl_xor_sync(0xffffffffu, q, o);
    }
    if ((tid & 31) == 0) { r1[tid >> 5] = s; r2[tid >> 5] = q; }
    __syncthreads();
    if (tid < 32) {
        float ss = (tid < 8) ? r1[tid] : 0.f;
        float qq = (tid < 8) ? r2[tid] : 0.f;
#pragma unroll
        for (int o = 4; o; o >>= 1) {
            ss += __shfl_xor_sync(0xffffffffu, ss, o);
            qq += __shfl_xor_sync(0xffffffffu, qq, o);
        }
        if (tid == 0) { r1[0] = ss; r2[0] = qq; }
    }
    __syncthreads();
    const float mean = r1[0] * (1.f / 1024.f);
    const float var  = r2[0] * (1.f / 1024.f) - mean * mean;
    const float rstd = rsqrtf(var + 1e-5f);

    float4 xv = *(const float4*)(x + base + tid * 4);
    float4 gv = *(const float4*)(gw + tid * 4);
    float4 bv = *(const float4*)(bw + tid * 4);
    float4 o;
    o.x = xv.x + (tv.x - mean) * rstd * gv.x + bv.x;
    o.y = xv.y + (tv.y - mean) * rstd * gv.y + bv.y;
    o.z = xv.z + (tv.z - mean) * rstd * gv.z + bv.z;
    o.w = xv.w + (tv.w - mean) * rstd * gv.w + bv.w;
    *(float4*)(out + base + tid * 4) = o;
}

// ---------------- launch ----------------
static float* sym_addr(const void* s) {
    void* p = nullptr;
    cudaGetSymbolAddress(&p, s);
    return (float*)p;
}

extern "C" void kernel_launch(void* const* d_in, const int* in_sizes, int n_in,
                              void* d_out, int out_size)
{
    (void)in_sizes; (void)n_in; (void)out_size;
    const float* x   = (const float*)d_in[0];
    const float* Wq  = (const float*)d_in[1];
    const float* bq  = (const float*)d_in[2];
    const float* Wk  = (const float*)d_in[3];
    const float* bk  = (const float*)d_in[4];
    const float* Wv  = (const float*)d_in[5];
    const float* bv  = (const float*)d_in[6];
    const float* Wo  = (const float*)d_in[7];
    const float* bo  = (const float*)d_in[8];
    const float* W1  = (const float*)d_in[9];
    const float* b1  = (const float*)d_in[10];
    const float* W2  = (const float*)d_in[11];
    const float* b2  = (const float*)d_in[12];
    const float* g1  = (const float*)d_in[13];
    const float* be1 = (const float*)d_in[14];
    const float* g2  = (const float*)d_in[15];
    const float* be2 = (const float*)d_in[16];
    float* out = (float*)d_out;

    float* q  = sym_addr(g_q);
    float* k  = sym_addr(g_k);
    float* v  = sym_addr(g_v);
    float* oc = sym_addr(g_oc);
    float* at = sym_addr(g_at);
    float* x1 = sym_addr(g_x1);
    float* ff = sym_addr(g_ff);
    float* ps = sym_addr(g_ps);

    const int GSM = 65536;                 // dense gemm dynamic smem
    const int FSM = (128*68*2 + 64*132 + 8*16*132) * 4;  // flash smem
    cudaFuncSetAttribute(gemm_tf32<2,1>, cudaFuncAttributeMaxDynamicSharedMemorySize, GSM);
    cudaFuncSetAttribute(gemm_tf32<0,0>, cudaFuncAttributeMaxDynamicSharedMemorySize, GSM);
    cudaFuncSetAttribute(flash_attn,     cudaFuncAttributeMaxDynamicSharedMemorySize, FSM);

    const dim3 blk(256);
    const float rs = 0.125f;  // 1/sqrt(DK)

    // QKV projections (scale folded into q)
    gemm_tf32<2,1><<<dim3(8,32), blk, GSM>>>(x, Wq, bq, q, 4096, 1024, 1024, rs,  0);
    gemm_tf32<2,1><<<dim3(8,32), blk, GSM>>>(x, Wk, bk, k, 4096, 1024, 1024, 1.f, 0);
    gemm_tf32<2,1><<<dim3(8,32), blk, GSM>>>(x, Wv, bv, v, 4096, 1024, 1024, 1.f, 0);

    // fused attention -> concat layout
    flash_attn<<<dim3(8,64), blk, FSM>>>(q, k, v, oc);

    // output projection
    gemm_tf32<0,0><<<dim3(8,32), blk, GSM>>>(oc, Wo, bo, at, 4096, 1024, 1024, 1.f, 0);
    add_ln_kernel<<<4096, blk>>>(x, at, g1, be1, x1);

    // FFN
    gemm_tf32<0,0><<<dim3(32,32), blk, GSM>>>(x1, W1, b1, ff, 4096, 4096, 1024, 1.f, 1);
    gemm_tf32<0,0><<<dim3(8,32), blk, GSM>>>(ff, W2, b2, ps, 4096, 1024, 4096, 1.f, 0);

    add_ln_kernel<<<4096, blk>>>(x1, ps, g2, be2, out);
}

// round 3
// speedup vs baseline: 3.5952x; 2.4395x over previous
#include <cuda_runtime.h>
#include <cuda_fp16.h>

#define BB 4
#define SS 1024
#define DD 1024
#define HH 16
#define DKC 64
#define DFF 4096

// ---------------- scratch ----------------
__device__ __half g_xh [BB*SS*DD];        // x in fp16
__device__ __half g_wq [DD*DD];           // packed [D, H*DK] fp16
__device__ __half g_wk [DD*DD];
__device__ __half g_wv [DD*DD];
__device__ __half g_wo [DD*DD];
__device__ __half g_w1 [DD*DFF];
__device__ __half g_w2 [DFF*DD];
__device__ __half g_q  [BB*HH*SS*DKC];    // [z][s][dk]
__device__ __half g_k  [BB*HH*SS*DKC];
__device__ __half g_vt [BB*HH*DKC*SS];    // [z][dk][s]
__device__ __half g_oc [BB*SS*DD];        // attn concat fp16
__device__ float  g_at [BB*SS*DD];
__device__ float  g_x1 [BB*SS*DD];
__device__ __half g_x1h[BB*SS*DD];
__device__ __half g_ff [BB*SS*DFF];
__device__ float  g_ps [BB*SS*DD];

// ---------------- asm helpers ----------------
__device__ __forceinline__ void ldm_x4(unsigned& r0, unsigned& r1, unsigned& r2, unsigned& r3, unsigned addr) {
    asm volatile("ldmatrix.sync.aligned.m8n8.x4.shared.b16 {%0,%1,%2,%3}, [%4];"
                 : "=r"(r0), "=r"(r1), "=r"(r2), "=r"(r3) : "r"(addr));
}
__device__ __forceinline__ void ldm_x2(unsigned& r0, unsigned& r1, unsigned addr) {
    asm volatile("ldmatrix.sync.aligned.m8n8.x2.shared.b16 {%0,%1}, [%2];"
                 : "=r"(r0), "=r"(r1) : "r"(addr));
}
__device__ __forceinline__ void ldm_x2t(unsigned& r0, unsigned& r1, unsigned addr) {
    asm volatile("ldmatrix.sync.aligned.m8n8.x2.trans.shared.b16 {%0,%1}, [%2];"
                 : "=r"(r0), "=r"(r1) : "r"(addr));
}
__device__ __forceinline__ void stm_x2(unsigned addr, unsigned r0, unsigned r1) {
    asm volatile("stmatrix.sync.aligned.m8n8.x2.shared.b16 [%0], {%1,%2};"
                 :: "r"(addr), "r"(r0), "r"(r1) : "memory");
}
__device__ __forceinline__ void mma16(float* c, const unsigned* a, const unsigned* b) {
    asm volatile(
        "mma.sync.aligned.m16n8k16.row.col.f32.f16.f16.f32 "
        "{%0,%1,%2,%3},{%4,%5,%6,%7},{%8,%9},{%0,%1,%2,%3};"
        : "+f"(c[0]), "+f"(c[1]), "+f"(c[2]), "+f"(c[3])
        : "r"(a[0]), "r"(a[1]), "r"(a[2]), "r"(a[3]), "r"(b[0]), "r"(b[1]));
}
__device__ __forceinline__ void cp16(unsigned dst, const void* src) {
    asm volatile("cp.async.cg.shared.global [%0], [%1], 16;" :: "r"(dst), "l"(src));
}
__device__ __forceinline__ void cp_commit() { asm volatile("cp.async.commit_group;" ::: "memory"); }
__device__ __forceinline__ void cp_wait0()  { asm volatile("cp.async.wait_group 0;" ::: "memory"); }
__device__ __forceinline__ void cp_wait2()  { asm volatile("cp.async.wait_group 2;" ::: "memory"); }

// ---------------- conversion kernels ----------------
__global__ void __launch_bounds__(256) cvt_half(const float* __restrict__ in,
                                                __half* __restrict__ out, int n) {
    int i = (blockIdx.x * 256 + threadIdx.x) * 4;
    if (i < n) {
        float4 v = *(const float4*)(in + i);
        __half2* o = (__half2*)(out + i);
        o[0] = __floats2half2_rn(v.x, v.y);
        o[1] = __floats2half2_rn(v.z, v.w);
    }
}
// W [H,D,DK] fp32 -> out [D, H*DK] fp16
__global__ void __launch_bounds__(256) cvt_qkvw(const float* __restrict__ in,
                                                __half* __restrict__ out) {
    int i = (blockIdx.x * 256 + threadIdx.x) * 4;   // over H*D*DK = 1M
    const int h = i >> 16;
    const int j = i & 65535;
    const int d = j >> 6, c = j & 63;
    float4 v = *(const float4*)(in + i);
    __half2* o = (__half2*)(out + d * 1024 + h * 64 + c);
    o[0] = __floats2half2_rn(v.x, v.y);
    o[1] = __floats2half2_rn(v.z, v.w);
}

// ---------------- fp16 tensor-core GEMM (4-stage cp.async) ----------------
// C = epi(A @ B + bias)   A: [M,K] half row-major,  B: [K,N] half row-major
// EPI 0: half out C[m*N+n], optional relu
// EPI 1: half out to [z=b*16+h][s][dk], v = (acc+bias)*alpha   (Q/K proj)
// EPI 2: float out C[m*N+n]
// EPI 3: half out transposed to [z][dk][s]                     (V proj)
#define AST 40
#define BST 136
#define STG_H (128*AST + 32*BST)   // 9472 halfs / stage
template<int EPI>
__global__ void __launch_bounds__(256, 2)
gemm_h(const __half* __restrict__ A, const __half* __restrict__ B,
       const float* __restrict__ bias, void* __restrict__ Cout,
       int M, int N, int K, float alpha, int relu)
{
    extern __shared__ __half sm[];
    const unsigned smB = (unsigned)__cvta_generic_to_shared(sm);

    const int tid  = threadIdx.x;
    const int lane = tid & 31;
    const int wid  = tid >> 5;
    const int wm   = wid & 1;
    const int wn   = wid >> 1;
    const int Rb = blockIdx.y * 128;
    const int Nb = blockIdx.x * 128;
    const int nK = K >> 5;

    auto issue = [&](int it) {
        if (it < nK) {
            const int s = it & 3;
            const unsigned sa = smB + (s * STG_H) * 2;
            const unsigned sb = sa + 128 * AST * 2;
#pragma unroll
            for (int i = 0; i < 2; i++) {
                const int c = tid + 256 * i;
                const int row = c >> 2, cc = (c & 3) * 8;
                cp16(sa + (row * AST + cc) * 2, A + (Rb + row) * K + it * 32 + cc);
            }
#pragma unroll
            for (int i = 0; i < 2; i++) {
                const int c = tid + 256 * i;
                const int kk = c >> 4, nc = (c & 15) * 8;
                cp16(sb + (kk * BST + nc) * 2, B + (it * 32 + kk) * N + Nb + nc);
            }
        }
        cp_commit();
    };

    float acc[4][4][4];
#pragma unroll
    for (int i = 0; i < 4; i++)
#pragma unroll
        for (int j = 0; j < 4; j++)
#pragma unroll
            for (int r = 0; r < 4; r++) acc[i][j][r] = 0.f;

    issue(0); issue(1); issue(2);

    const int lr = lane & 15;
    const int lh = (lane >> 4) << 3;

    for (int it = 0; it < nK; it++) {
        cp_wait2();
        __syncthreads();
        issue(it + 3);

        const int s = it & 3;
        const unsigned sa = smB + (s * STG_H) * 2;
        const unsigned sb = sa + 128 * AST * 2;
#pragma unroll
        for (int k16 = 0; k16 < 2; k16++) {
            const int k0 = k16 * 16;
            unsigned af[4][4], bf[4][2];
#pragma unroll
            for (int mt = 0; mt < 4; mt++)
                ldm_x4(af[mt][0], af[mt][1], af[mt][2], af[mt][3],
                       sa + ((wm * 64 + mt * 16 + lr) * AST + k0 + lh) * 2);
#pragma unroll
            for (int nt = 0; nt < 4; nt++)
                ldm_x2t(bf[nt][0], bf[nt][1],
                        sb + ((k0 + lr) * BST + wn * 32 + nt * 8) * 2);
#pragma unroll
            for (int mt = 0; mt < 4; mt++)
#pragma unroll
                for (int nt = 0; nt < 4; nt++)
                    mma16(acc[mt][nt], af[mt], bf[nt]);
        }
    }

    // epilogue
    const int tq = lane & 3, gq = lane >> 2;
#pragma unroll
    for (int mt = 0; mt < 4; mt++) {
#pragma unroll
        for (int nt = 0; nt < 4; nt++) {
            const int m0 = Rb + wm * 64 + mt * 16 + gq;
            const int n0 = Nb + wn * 32 + nt * 8 + tq * 2;
            const float b0 = bias ? bias[n0] : 0.f;
            const float b1 = bias ? bias[n0 + 1] : 0.f;
#pragma unroll
            for (int half = 0; half < 2; half++) {
                const int m = m0 + half * 8;
                float v0 = (acc[mt][nt][half * 2 + 0] + b0) * alpha;
                float v1 = (acc[mt][nt][half * 2 + 1] + b1) * alpha;
                if (relu) { v0 = fmaxf(v0, 0.f); v1 = fmaxf(v1, 0.f); }
                if (EPI == 0) {
                    *(__half2*)((__half*)Cout + m * N + n0) = __floats2half2_rn(v0, v1);
                } else if (EPI == 2) {
                    *(float2*)((float*)Cout + m * N + n0) = make_float2(v0, v1);
                } else if (EPI == 1) {
                    const int b = m >> 10, sI = m & 1023;
                    const int h = n0 >> 6, dk = n0 & 63;
                    *(__half2*)((__half*)Cout + ((b * 16 + h) * 1024 + sI) * 64 + dk) =
                        __floats2half2_rn(v0, v1);
                } else { // EPI 3: transposed V
                    const int b = m >> 10, sI = m & 1023;
                    const int h = n0 >> 6, dk = n0 & 63;
                    __half* base = (__half*)Cout + (b * 16 + h) * 65536;
                    base[dk * 1024 + sI]       = __float2half(v0);
                    base[(dk + 1) * 1024 + sI] = __float2half(v1);
                }
            }
        }
    }
}

// ---------------- fp16 flash attention ----------------
// Q,K: [z][1024][64] half (q pre-scaled), Vt: [z][64][1024] half
// O: [b*1024+s][h*64+dk] half
#define QST 72
#define VST 136
#define OFF_K  (128*QST)
#define OFF_VT (OFF_K + 128*QST)
#define OFF_P  (OFF_VT + 64*VST)
#define FL_SMH (OFF_P + 128*VST)
__global__ void __launch_bounds__(256, 2)
flash_h(const __half* __restrict__ Qg, const __half* __restrict__ Kg,
        const __half* __restrict__ Vg, __half* __restrict__ O)
{
    extern __shared__ __half sm[];
    const unsigned smB = (unsigned)__cvta_generic_to_shared(sm);
    const unsigned sQ = smB, sK = smB + OFF_K * 2, sVT = smB + OFF_VT * 2, sP = smB + OFF_P * 2;

    const int tid = threadIdx.x, lane = tid & 31, wid = tid >> 5;
    const int tq = lane & 3, gq = lane >> 2;
    const int lr = lane & 15, lh = (lane >> 4) << 3;
    const int l7 = lane & 7, l8 = ((lane >> 3) & 1) << 3;
    const int z = blockIdx.y, qt = blockIdx.x;

    const __half* Qp = Qg + (z * 1024 + qt * 128) * 64;
    const __half* Kp = Kg + z * 1024 * 64;
    const __half* Vp = Vg + z * 65536;

    auto stageKV = [&](int kt) {
#pragma unroll
        for (int i = 0; i < 4; i++) {
            const int c = tid + 256 * i;
            const int row = c >> 3, cc = (c & 7) * 8;
            cp16(sK + (row * QST + cc) * 2, Kp + (kt * 128 + row) * 64 + cc);
        }
#pragma unroll
        for (int i = 0; i < 4; i++) {
            const int c = tid + 256 * i;
            const int row = c >> 4, cc = (c & 15) * 8;
            cp16(sVT + (row * VST + cc) * 2, Vp + row * 1024 + kt * 128 + cc);
        }
    };

    // prologue: Q + first K/V
#pragma unroll
    for (int i = 0; i < 4; i++) {
        const int c = tid + 256 * i;
        const int row = c >> 3, cc = (c & 7) * 8;
        cp16(sQ + (row * QST + cc) * 2, Qp + row * 64 + cc);
    }
    stageKV(0);
    cp_commit(); cp_wait0();
    __syncthreads();

    float oacc[8][4];
#pragma unroll
    for (int i = 0; i < 8; i++)
#pragma unroll
        for (int j = 0; j < 4; j++) oacc[i][j] = 0.f;
    float mrow0 = -1e30f, mrow1 = -1e30f, lrow0 = 0.f, lrow1 = 0.f;

    for (int kt = 0; kt < 8; kt++) {
        // ---- S = Q @ K^T ----
        float sacc[16][4];
#pragma unroll
        for (int i = 0; i < 16; i++)
#pragma unroll
            for (int j = 0; j < 4; j++) sacc[i][j] = 0.f;
#pragma unroll
        for (int k16 = 0; k16 < 4; k16++) {
            const int k0 = k16 * 16;
            unsigned a[4];
            ldm_x4(a[0], a[1], a[2], a[3], sQ + ((wid * 16 + lr) * QST + k0 + lh) * 2);
#pragma unroll
            for (int nt = 0; nt < 16; nt++) {
                unsigned b[2];
                ldm_x2(b[0], b[1], sK + ((nt * 8 + l7) * QST + k0 + l8) * 2);
                mma16(sacc[nt], a, b);
            }
        }

        // ---- online softmax ----
        float m0 = -1e30f, m1 = -1e30f;
#pragma unroll
        for (int nt = 0; nt < 16; nt++) {
            m0 = fmaxf(m0, fmaxf(sacc[nt][0], sacc[nt][1]));
            m1 = fmaxf(m1, fmaxf(sacc[nt][2], sacc[nt][3]));
        }
        m0 = fmaxf(m0, __shfl_xor_sync(0xffffffffu, m0, 1));
        m0 = fmaxf(m0, __shfl_xor_sync(0xffffffffu, m0, 2));
        m1 = fmaxf(m1, __shfl_xor_sync(0xffffffffu, m1, 1));
        m1 = fmaxf(m1, __shfl_xor_sync(0xffffffffu, m1, 2));
        const float mn0 = fmaxf(mrow0, m0), mn1 = fmaxf(mrow1, m1);
        const float sc0 = __expf(mrow0 - mn0), sc1 = __expf(mrow1 - mn1);

        float rs0 = 0.f, rs1 = 0.f;
        const unsigned pAddr = sP + ((wid * 16 + lr) * VST) * 2;
#pragma unroll
        for (int nt = 0; nt < 16; nt++) {
            const float p0 = __expf(sacc[nt][0] - mn0);
            const float p1 = __expf(sacc[nt][1] - mn0);
            const float p2 = __expf(sacc[nt][2] - mn1);
            const float p3 = __expf(sacc[nt][3] - mn1);
            rs0 += p0 + p1; rs1 += p2 + p3;
            __half2 h01 = __floats2half2_rn(p0, p1);
            __half2 h23 = __floats2half2_rn(p2, p3);
            stm_x2(pAddr + nt * 16, *(unsigned*)&h01, *(unsigned*)&h23);
        }
        rs0 += __shfl_xor_sync(0xffffffffu, rs0, 1);
        rs0 += __shfl_xor_sync(0xffffffffu, rs0, 2);
        rs1 += __shfl_xor_sync(0xffffffffu, rs1, 1);
        rs1 += __shfl_xor_sync(0xffffffffu, rs1, 2);
        lrow0 = lrow0 * sc0 + rs0;
        lrow1 = lrow1 * sc1 + rs1;
        mrow0 = mn0; mrow1 = mn1;
#pragma unroll
        for (int nt = 0; nt < 8; nt++) {
            oacc[nt][0] *= sc0; oacc[nt][1] *= sc0;
            oacc[nt][2] *= sc1; oacc[nt][3] *= sc1;
        }
        __syncwarp();

        // ---- O += P @ V ----
#pragma unroll
        for (int k16 = 0; k16 < 8; k16++) {
            const int k0 = k16 * 16;
            unsigned a[4];
            ldm_x4(a[0], a[1], a[2], a[3], sP + ((wid * 16 + lr) * VST + k0 + lh) * 2);
#pragma unroll
            for (int nt = 0; nt < 8; nt++) {
                unsigned b[2];
                ldm_x2(b[0], b[1], sVT + ((nt * 8 + l7) * VST + k0 + l8) * 2);
                mma16(oacc[nt], a, b);
            }
        }

        if (kt < 7) {
            __syncthreads();            // all warps done reading sK/sVT
            stageKV(kt + 1);
            cp_commit(); cp_wait0();
            __syncthreads();
        }
    }

    // epilogue
    const float i0 = 1.f / lrow0, i1 = 1.f / lrow1;
    const int b = z >> 4, h = z & 15;
    const int s0 = qt * 128 + wid * 16 + gq;
#pragma unroll
    for (int nt = 0; nt < 8; nt++) {
        const int col = h * 64 + nt * 8 + 2 * tq;
        *(__half2*)&O[(b * 1024 + s0) * 1024 + col] =
            __floats2half2_rn(oacc[nt][0] * i0, oacc[nt][1] * i0);
        *(__half2*)&O[(b * 1024 + s0 + 8) * 1024 + col] =
            __floats2half2_rn(oacc[nt][2] * i1, oacc[nt][3] * i1);
    }
}

// ---------------- out = x + LayerNorm(t)*g + b  (+ optional fp16 copy) ----------------
__global__ void __launch_bounds__(256)
add_ln_kernel(const float* __restrict__ x, const float* __restrict__ t,
              const float* __restrict__ gw, const float* __restrict__ bw,
              float* __restrict__ out, __half* __restrict__ outh)
{
    __shared__ float r1[8], r2[8];
    const int base = blockIdx.x * 1024;
    const int tid = threadIdx.x;
    float4 tv = *(const float4*)(t + base + tid * 4);
    float s = tv.x + tv.y + tv.z + tv.w;
    float q = tv.x * tv.x + tv.y * tv.y + tv.z * tv.z + tv.w * tv.w;
#pragma unroll
    for (int o = 16; o; o >>= 1) {
        s += __shfl_xor_sync(0xffffffffu, s, o);
        q += __shfl_xor_sync(0xffffffffu, q, o);
    }
    if ((tid & 31) == 0) { r1[tid >> 5] = s; r2[tid >> 5] = q; }
    __syncthreads();
    if (tid < 32) {
        float ss = (tid < 8) ? r1[tid] : 0.f;
        float qq = (tid < 8) ? r2[tid] : 0.f;
#pragma unroll
        for (int o = 4; o; o >>= 1) {
            ss += __shfl_xor_sync(0xffffffffu, ss, o);
            qq += __shfl_xor_sync(0xffffffffu, qq, o);
        }
        if (tid == 0) { r1[0] = ss; r2[0] = qq; }
    }
    __syncthreads();
    const float mean = r1[0] * (1.f / 1024.f);
    const float var  = r2[0] * (1.f / 1024.f) - mean * mean;
    const float rstd = rsqrtf(var + 1e-5f);

    float4 xv = *(const float4*)(x + base + tid * 4);
    float4 gv = *(const float4*)(gw + tid * 4);
    float4 bv = *(const float4*)(bw + tid * 4);
    float4 o;
    o.x = xv.x + (tv.x - mean) * rstd * gv.x + bv.x;
    o.y = xv.y + (tv.y - mean) * rstd * gv.y + bv.y;
    o.z = xv.z + (tv.z - mean) * rstd * gv.z + bv.z;
    o.w = xv.w + (tv.w - mean) * rstd * gv.w + bv.w;
    *(float4*)(out + base + tid * 4) = o;
    if (outh) {
        __half2* oh = (__half2*)(outh + base + tid * 4);
        oh[0] = __floats2half2_rn(o.x, o.y);
        oh[1] = __floats2half2_rn(o.z, o.w);
    }
}

// ---------------- launch ----------------
template<class T>
static T* sym_addr(const void* s) {
    void* p = nullptr;
    cudaGetSymbolAddress(&p, s);
    return (T*)p;
}

extern "C" void kernel_launch(void* const* d_in, const int* in_sizes, int n_in,
                              void* d_out, int out_size)
{
    (void)in_sizes; (void)n_in; (void)out_size;
    const float* x   = (const float*)d_in[0];
    const float* Wq  = (const float*)d_in[1];
    const float* bq  = (const float*)d_in[2];
    const float* Wk  = (const float*)d_in[3];
    const float* bk  = (const float*)d_in[4];
    const float* Wv  = (const float*)d_in[5];
    const float* bv  = (const float*)d_in[6];
    const float* Wo  = (const float*)d_in[7];
    const float* bo  = (const float*)d_in[8];
    const float* W1  = (const float*)d_in[9];
    const float* b1  = (const float*)d_in[10];
    const float* W2  = (const float*)d_in[11];
    const float* b2  = (const float*)d_in[12];
    const float* g1  = (const float*)d_in[13];
    const float* be1 = (const float*)d_in[14];
    const float* g2  = (const float*)d_in[15];
    const float* be2 = (const float*)d_in[16];
    float* out = (float*)d_out;

    __half* xh  = sym_addr<__half>(g_xh);
    __half* wq  = sym_addr<__half>(g_wq);
    __half* wk  = sym_addr<__half>(g_wk);
    __half* wv  = sym_addr<__half>(g_wv);
    __half* wo  = sym_addr<__half>(g_wo);
    __half* w1  = sym_addr<__half>(g_w1);
    __half* w2  = sym_addr<__half>(g_w2);
    __half* q   = sym_addr<__half>(g_q);
    __half* k   = sym_addr<__half>(g_k);
    __half* vt  = sym_addr<__half>(g_vt);
    __half* oc  = sym_addr<__half>(g_oc);
    float*  at  = sym_addr<float>(g_at);
    float*  x1  = sym_addr<float>(g_x1);
    __half* x1h = sym_addr<__half>(g_x1h);
    __half* ff  = sym_addr<__half>(g_ff);
    float*  ps  = sym_addr<float>(g_ps);

    const int GSM = 4 * STG_H * 2;      // 75776 B
    const int FSM = FL_SMH * 2;         // 89088 B
    cudaFuncSetAttribute(gemm_h<0>, cudaFuncAttributeMaxDynamicSharedMemorySize, GSM);
    cudaFuncSetAttribute(gemm_h<1>, cudaFuncAttributeMaxDynamicSharedMemorySize, GSM);
    cudaFuncSetAttribute(gemm_h<2>, cudaFuncAttributeMaxDynamicSharedMemorySize, GSM);
    cudaFuncSetAttribute(gemm_h<3>, cudaFuncAttributeMaxDynamicSharedMemorySize, GSM);
    cudaFuncSetAttribute(flash_h,   cudaFuncAttributeMaxDynamicSharedMemorySize, FSM);

    const dim3 blk(256);

    // conversions
    cvt_half<<<4096, blk>>>(x,  xh, 4194304);
    cvt_qkvw<<<1024, blk>>>(Wq, wq);
    cvt_qkvw<<<1024, blk>>>(Wk, wk);
    cvt_qkvw<<<1024, blk>>>(Wv, wv);
    cvt_half<<<1024, blk>>>(Wo, wo, 1048576);
    cvt_half<<<4096, blk>>>(W1, w1, 4194304);
    cvt_half<<<4096, blk>>>(W2, w2, 4194304);

    // QKV projections (scale folded into q)
    gemm_h<1><<<dim3(8, 32), blk, GSM>>>(xh, wq, bq, q,  4096, 1024, 1024, 0.125f, 0);
    gemm_h<1><<<dim3(8, 32), blk, GSM>>>(xh, wk, bk, k,  4096, 1024, 1024, 1.f,    0);
    gemm_h<3><<<dim3(8, 32), blk, GSM>>>(xh, wv, bv, vt, 4096, 1024, 1024, 1.f,    0);

    // fused attention
    flash_h<<<dim3(8, 64), blk, FSM>>>(q, k, vt, oc);

    // output projection + LN
    gemm_h<2><<<dim3(8, 32), blk, GSM>>>(oc, wo, bo, at, 4096, 1024, 1024, 1.f, 0);
    add_ln_kernel<<<4096, blk>>>(x, at, g1, be1, x1, x1h);

    // FFN
    gemm_h<0><<<dim3(32, 32), blk, GSM>>>(x1h, w1, b1, ff, 4096, 4096, 1024, 1.f, 1);
    gemm_h<2><<<dim3(8, 32), blk, GSM>>>(ff,  w2, b2, ps, 4096, 1024, 4096, 1.f, 0);

    add_ln_kernel<<<4096, blk>>>(x1, ps, g2, be2, out, nullptr);
}

// round 5
// speedup vs baseline: 3.7720x; 1.0492x over previous
#include <cuda_runtime.h>
#include <cuda_fp16.h>

#define BB 4
#define SS 1024
#define DD 1024
#define HH 16
#define DKC 64
#define DFF 4096

// ---------------- scratch ----------------
__device__ __half g_xh  [BB*SS*DD];         // x fp16 [M,K]
__device__ __half g_wqkv[3*DD*DD];          // packed [3072 n][1024 k] fp16 (q,k,v)
__device__ __half g_wo  [DD*DD];            // [N,K] fp16
__device__ __half g_w1  [DFF*DD];           // [4096,1024]
__device__ __half g_w2  [DD*DFF];           // [1024,4096]
__device__ __half g_q   [BB*HH*SS*DKC];     // [z][s][dk]
__device__ __half g_k   [BB*HH*SS*DKC];
__device__ __half g_vt  [BB*HH*DKC*SS];     // [z][dk][s]
__device__ __half g_oc  [BB*SS*DD];         // attn concat fp16
__device__ float  g_at  [BB*SS*DD];
__device__ float  g_x1  [BB*SS*DD];
__device__ __half g_x1h [BB*SS*DD];
__device__ __half g_ff  [BB*SS*DFF];
__device__ float  g_ps  [BB*SS*DD];

// ---------------- asm helpers ----------------
__device__ __forceinline__ void cp16(unsigned dst, const void* src) {
    asm volatile("cp.async.cg.shared.global [%0], [%1], 16;" :: "r"(dst), "l"(src));
}
__device__ __forceinline__ void cp_commit() { asm volatile("cp.async.commit_group;" ::: "memory"); }
__device__ __forceinline__ void cp_wait0()  { asm volatile("cp.async.wait_group 0;" ::: "memory"); }
__device__ __forceinline__ void cp_wait1()  { asm volatile("cp.async.wait_group 1;" ::: "memory"); }

__device__ __forceinline__ void ldm_x4(unsigned& r0, unsigned& r1, unsigned& r2, unsigned& r3, unsigned addr) {
    asm volatile("ldmatrix.sync.aligned.m8n8.x4.shared.b16 {%0,%1,%2,%3}, [%4];"
                 : "=r"(r0), "=r"(r1), "=r"(r2), "=r"(r3) : "r"(addr));
}
__device__ __forceinline__ void ldm_x2(unsigned& r0, unsigned& r1, unsigned addr) {
    asm volatile("ldmatrix.sync.aligned.m8n8.x2.shared.b16 {%0,%1}, [%2];"
                 : "=r"(r0), "=r"(r1) : "r"(addr));
}
__device__ __forceinline__ void stm_x2(unsigned addr, unsigned r0, unsigned r1) {
    asm volatile("stmatrix.sync.aligned.m8n8.x2.shared.b16 [%0], {%1,%2};"
                 :: "r"(addr), "r"(r0), "r"(r1) : "memory");
}
__device__ __forceinline__ void mma16(float* c, const unsigned* a, const unsigned* b) {
    asm volatile(
        "mma.sync.aligned.m16n8k16.row.col.f32.f16.f16.f32 "
        "{%0,%1,%2,%3},{%4,%5,%6,%7},{%8,%9},{%0,%1,%2,%3};"
        : "+f"(c[0]), "+f"(c[1]), "+f"(c[2]), "+f"(c[3])
        : "r"(a[0]), "r"(a[1]), "r"(a[2]), "r"(a[3]), "r"(b[0]), "r"(b[1]));
}

// ---------------- conversion kernels ----------------
__global__ void __launch_bounds__(256) cvt_half(const float* __restrict__ in,
                                                __half* __restrict__ out, int n) {
    int i = (blockIdx.x * 256 + threadIdx.x) * 4;
    if (i < n) {
        float4 v = *(const float4*)(in + i);
        __half2* o = (__half2*)(out + i);
        o[0] = __floats2half2_rn(v.x, v.y);
        o[1] = __floats2half2_rn(v.z, v.w);
    }
}
// [K,N] fp32 row-major -> [N,K] fp16
__global__ void __launch_bounds__(256) trh(const float* __restrict__ in,
                                           __half* __restrict__ out, int K, int N) {
    __shared__ float t[32][33];
    const int tx = threadIdx.x, ty = threadIdx.y;
    const int n0 = blockIdx.x * 32, k0 = blockIdx.y * 32;
#pragma unroll
    for (int j = 0; j < 4; j++)
        t[ty + 8 * j][tx] = in[(k0 + ty + 8 * j) * N + n0 + tx];
    __syncthreads();
#pragma unroll
    for (int j = 0; j < 4; j++)
        out[(n0 + ty + 8 * j) * K + k0 + tx] = __float2half(t[tx][ty + 8 * j]);
}
// W [H,D,DK] fp32 -> out [n=h*64+dk][k=d] fp16
__global__ void __launch_bounds__(256) trh_qkv(const float* __restrict__ in,
                                               __half* __restrict__ out) {
    __shared__ float t[32][33];
    const int tx = threadIdx.x, ty = threadIdx.y;
    const int dk0 = blockIdx.x * 32, d0 = blockIdx.y * 32, h = blockIdx.z;
    const float* ip = in + h * 65536;
#pragma unroll
    for (int j = 0; j < 4; j++)
        t[ty + 8 * j][tx] = ip[(d0 + ty + 8 * j) * 64 + dk0 + tx];
    __syncthreads();
#pragma unroll
    for (int j = 0; j < 4; j++)
        out[(h * 64 + dk0 + ty + 8 * j) * 1024 + d0 + tx] = __float2half(t[tx][ty + 8 * j]);
}

// ---------------- fp16 GEMM: A[M,K] @ Bt[N,K]^T, k-major SW128 tiles ----------------
// 128x128 CTA tile, 64-k stages, 3 smem buffers, 8 warps (64x32 warp tile).
// EPI 0: half out (+relu)   EPI 1: fused QKV scatter (q,k half; v transposed)
// EPI 2: float out
#define STG_B 32768          // bytes per stage (A 16KB + B 16KB)
#define G2SM  (3*STG_B)
// swizzled addr within a k-major tile: row stride 128B, 16B blocks XOR row&7
__device__ __forceinline__ unsigned tswz(int row, int kbyte) {
    return (unsigned)(row * 128 + ((kbyte ^ ((row & 7) << 4)) & 127) + (kbyte & ~127));
}

template<int EPI>
__global__ void __launch_bounds__(256, 2)
gemm_h2(const __half* __restrict__ A, const __half* __restrict__ Bt,
        const float* __restrict__ b0p, const float* __restrict__ b1p,
        const float* __restrict__ b2p, void* __restrict__ C0,
        void* __restrict__ C1, void* __restrict__ C2,
        int M, int N, int K, int relu)
{
    extern __shared__ char dsm[];
    const unsigned smB = (unsigned)__cvta_generic_to_shared(dsm);

    const int tid = threadIdx.x, lane = tid & 31, wid = tid >> 5;
    const int wm = wid & 1, wn = wid >> 1;
    const int Rb = blockIdx.y * 128;
    const int Nb = blockIdx.x * 128;
    const int nS = K >> 6;

    const int crow = tid >> 3, ckc = (tid & 7) * 16;   // cp.async mapping
    const int lr = lane & 15, lhb = ((lane >> 4) << 4);  // ldmatrix mapping (bytes)

    auto issue = [&](int it) {
        const unsigned sA = smB + (it % 3) * STG_B;
        const unsigned sB = sA + 16384;
        const __half* Ap = A + (Rb + crow) * K + it * 64 + ckc / 2;
        const __half* Bp = Bt + (Nb + crow) * K + it * 64 + ckc / 2;
#pragma unroll
        for (int i = 0; i < 4; i++)
            cp16(sA + tswz(crow + 32 * i, ckc), Ap + 32 * i * K);
#pragma unroll
        for (int i = 0; i < 4; i++)
            cp16(sB + tswz(crow + 32 * i, ckc), Bp + 32 * i * K);
    };

    float acc[4][4][4];
#pragma unroll
    for (int i = 0; i < 4; i++)
#pragma unroll
        for (int j = 0; j < 4; j++)
#pragma unroll
            for (int r = 0; r < 4; r++) acc[i][j][r] = 0.f;

    issue(0); cp_commit();
    issue(1); cp_commit();

    for (int it = 0; it < nS; it++) {
        cp_wait1();
        __syncthreads();
        if (it + 2 < nS) issue(it + 2);
        cp_commit();

        const unsigned sA = smB + (it % 3) * STG_B;
        const unsigned sB = sA + 16384;
#pragma unroll
        for (int s = 0; s < 4; s++) {
            const int kb = s * 32;          // byte offset of k16 step
            unsigned af[4][4], bf[2][4];
#pragma unroll
            for (int mt = 0; mt < 4; mt++)
                ldm_x4(af[mt][0], af[mt][1], af[mt][2], af[mt][3],
                       sA + tswz(wm * 64 + mt * 16 + lr, kb + lhb));
#pragma unroll
            for (int nt2 = 0; nt2 < 2; nt2++)
                ldm_x4(bf[nt2][0], bf[nt2][1], bf[nt2][2], bf[nt2][3],
                       sB + tswz(wn * 32 + nt2 * 16 + lr, kb + lhb));
#pragma unroll
            for (int mt = 0; mt < 4; mt++)
#pragma unroll
                for (int nt = 0; nt < 4; nt++) {
                    unsigned b[2] = { bf[nt >> 1][nt & 1], bf[nt >> 1][(nt & 1) + 2] };
                    mma16(acc[mt][nt], af[mt], b);
                }
        }
    }

    // ---- epilogue ----
    const int tq = lane & 3, gq = lane >> 2;
#pragma unroll
    for (int mt = 0; mt < 4; mt++) {
#pragma unroll
        for (int nt = 0; nt < 4; nt++) {
            const int m0 = Rb + wm * 64 + mt * 16 + gq;
            const int n0 = Nb + wn * 32 + nt * 8 + tq * 2;
            float bb0 = 0.f, bb1 = 0.f, alpha = 1.f;
            int seg = 0, nn = n0;
            if (EPI == 1) {
                seg = n0 >> 10; nn = n0 & 1023;
                const float* bp = seg == 0 ? b0p : (seg == 1 ? b1p : b2p);
                const int hh = nn >> 6, dk = nn & 63;
                bb0 = bp[hh * 64 + dk]; bb1 = bp[hh * 64 + dk + 1];
                if (seg == 0) alpha = 0.125f;
            } else if (b0p) {
                bb0 = b0p[n0]; bb1 = b0p[n0 + 1];
            }
#pragma unroll
            for (int half = 0; half < 2; half++) {
                const int m = m0 + half * 8;
                float v0 = (acc[mt][nt][half * 2 + 0] + bb0) * alpha;
                float v1 = (acc[mt][nt][half * 2 + 1] + bb1) * alpha;
                if (relu) { v0 = fmaxf(v0, 0.f); v1 = fmaxf(v1, 0.f); }
                if (EPI == 0) {
                    *(__half2*)((__half*)C0 + m * N + n0) = __floats2half2_rn(v0, v1);
                } else if (EPI == 2) {
                    *(float2*)((float*)C0 + m * N + n0) = make_float2(v0, v1);
                } else {
                    const int b = m >> 10, s = m & 1023;
                    const int hh = nn >> 6, dk = nn & 63;
                    if (seg == 0) {
                        *(__half2*)((__half*)C0 + ((b * 16 + hh) * 1024 + s) * 64 + dk) =
                            __floats2half2_rn(v0, v1);
                    } else if (seg == 1) {
                        *(__half2*)((__half*)C1 + ((b * 16 + hh) * 1024 + s) * 64 + dk) =
                            __floats2half2_rn(v0, v1);
                    } else {
                        __half* vp = (__half*)C2 + (b * 16 + hh) * 65536 + s;
                        vp[dk * 1024]       = __float2half(v0);
                        vp[(dk + 1) * 1024] = __float2half(v1);
                    }
                }
            }
        }
    }
}

// ---------------- fp16 flash attention (unchanged from R3) ----------------
#define QST 72
#define VST 136
#define OFF_K  (128*QST)
#define OFF_VT (OFF_K + 128*QST)
#define OFF_P  (OFF_VT + 64*VST)
#define FL_SMH (OFF_P + 128*VST)
__global__ void __launch_bounds__(256, 2)
flash_h(const __half* __restrict__ Qg, const __half* __restrict__ Kg,
        const __half* __restrict__ Vg, __half* __restrict__ O)
{
    extern __shared__ __half sm[];
    const unsigned smB = (unsigned)__cvta_generic_to_shared(sm);
    const unsigned sQ = smB, sK = smB + OFF_K * 2, sVT = smB + OFF_VT * 2, sP = smB + OFF_P * 2;

    const int tid = threadIdx.x, lane = tid & 31, wid = tid >> 5;
    const int tq = lane & 3, gq = lane >> 2;
    const int lr = lane & 15, lh = (lane >> 4) << 3;
    const int l7 = lane & 7, l8 = ((lane >> 3) & 1) << 3;
    const int z = blockIdx.y, qt = blockIdx.x;

    const __half* Qp = Qg + (z * 1024 + qt * 128) * 64;
    const __half* Kp = Kg + z * 1024 * 64;
    const __half* Vp = Vg + z * 65536;

    auto stageKV = [&](int kt) {
#pragma unroll
        for (int i = 0; i < 4; i++) {
            const int c = tid + 256 * i;
            const int row = c >> 3, cc = (c & 7) * 8;
            cp16(sK + (row * QST + cc) * 2, Kp + (kt * 128 + row) * 64 + cc);
        }
#pragma unroll
        for (int i = 0; i < 4; i++) {
            const int c = tid + 256 * i;
            const int row = c >> 4, cc = (c & 15) * 8;
            cp16(sVT + (row * VST + cc) * 2, Vp + row * 1024 + kt * 128 + cc);
        }
    };

#pragma unroll
    for (int i = 0; i < 4; i++) {
        const int c = tid + 256 * i;
        const int row = c >> 3, cc = (c & 7) * 8;
        cp16(sQ + (row * QST + cc) * 2, Qp + row * 64 + cc);
    }
    stageKV(0);
    cp_commit(); cp_wait0();
    __syncthreads();

    float oacc[8][4];
#pragma unroll
    for (int i = 0; i < 8; i++)
#pragma unroll
        for (int j = 0; j < 4; j++) oacc[i][j] = 0.f;
    float mrow0 = -1e30f, mrow1 = -1e30f, lrow0 = 0.f, lrow1 = 0.f;

    for (int kt = 0; kt < 8; kt++) {
        float sacc[16][4];
#pragma unroll
        for (int i = 0; i < 16; i++)
#pragma unroll
            for (int j = 0; j < 4; j++) sacc[i][j] = 0.f;
#pragma unroll
        for (int k16 = 0; k16 < 4; k16++) {
            const int k0 = k16 * 16;
            unsigned a[4];
            ldm_x4(a[0], a[1], a[2], a[3], sQ + ((wid * 16 + lr) * QST + k0 + lh) * 2);
#pragma unroll
            for (int nt = 0; nt < 16; nt++) {
                unsigned b[2];
                ldm_x2(b[0], b[1], sK + ((nt * 8 + l7) * QST + k0 + l8) * 2);
                mma16(sacc[nt], a, b);
            }
        }

        float m0 = -1e30f, m1 = -1e30f;
#pragma unroll
        for (int nt = 0; nt < 16; nt++) {
            m0 = fmaxf(m0, fmaxf(sacc[nt][0], sacc[nt][1]));
            m1 = fmaxf(m1, fmaxf(sacc[nt][2], sacc[nt][3]));
        }
        m0 = fmaxf(m0, __shfl_xor_sync(0xffffffffu, m0, 1));
        m0 = fmaxf(m0, __shfl_xor_sync(0xffffffffu, m0, 2));
        m1 = fmaxf(m1, __shfl_xor_sync(0xffffffffu, m1, 1));
        m1 = fmaxf(m1, __shfl_xor_sync(0xffffffffu, m1, 2));
        const float mn0 = fmaxf(mrow0, m0), mn1 = fmaxf(mrow1, m1);
        const float sc0 = __expf(mrow0 - mn0), sc1 = __expf(mrow1 - mn1);

        float rs0 = 0.f, rs1 = 0.f;
        const unsigned pAddr = sP + ((wid * 16 + lr) * VST) * 2;
#pragma unroll
        for (int nt = 0; nt < 16; nt++) {
            const float p0 = __expf(sacc[nt][0] - mn0);
            const float p1 = __expf(sacc[nt][1] - mn0);
            const float p2 = __expf(sacc[nt][2] - mn1);
            const float p3 = __expf(sacc[nt][3] - mn1);
            rs0 += p0 + p1; rs1 += p2 + p3;
            __half2 h01 = __floats2half2_rn(p0, p1);
            __half2 h23 = __floats2half2_rn(p2, p3);
            stm_x2(pAddr + nt * 16, *(unsigned*)&h01, *(unsigned*)&h23);
        }
        rs0 += __shfl_xor_sync(0xffffffffu, rs0, 1);
        rs0 += __shfl_xor_sync(0xffffffffu, rs0, 2);
        rs1 += __shfl_xor_sync(0xffffffffu, rs1, 1);
        rs1 += __shfl_xor_sync(0xffffffffu, rs1, 2);
        lrow0 = lrow0 * sc0 + rs0;
        lrow1 = lrow1 * sc1 + rs1;
        mrow0 = mn0; mrow1 = mn1;
#pragma unroll
        for (int nt = 0; nt < 8; nt++) {
            oacc[nt][0] *= sc0; oacc[nt][1] *= sc0;
            oacc[nt][2] *= sc1; oacc[nt][3] *= sc1;
        }
        __syncwarp();

#pragma unroll
        for (int k16 = 0; k16 < 8; k16++) {
            const int k0 = k16 * 16;
            unsigned a[4];
            ldm_x4(a[0], a[1], a[2], a[3], sP + ((wid * 16 + lr) * VST + k0 + lh) * 2);
#pragma unroll
            for (int nt = 0; nt < 8; nt++) {
                unsigned b[2];
                ldm_x2(b[0], b[1], sVT + ((nt * 8 + l7) * VST + k0 + l8) * 2);
                mma16(oacc[nt], a, b);
            }
        }

        if (kt < 7) {
            __syncthreads();
            stageKV(kt + 1);
            cp_commit(); cp_wait0();
            __syncthreads();
        }
    }

    const float i0 = 1.f / lrow0, i1 = 1.f / lrow1;
    const int b = z >> 4, h = z & 15;
    const int s0 = qt * 128 + wid * 16 + gq;
#pragma unroll
    for (int nt = 0; nt < 8; nt++) {
        const int col = h * 64 + nt * 8 + 2 * tq;
        *(__half2*)&O[(b * 1024 + s0) * 1024 + col] =
            __floats2half2_rn(oacc[nt][0] * i0, oacc[nt][1] * i0);
        *(__half2*)&O[(b * 1024 + s0 + 8) * 1024 + col] =
            __floats2half2_rn(oacc[nt][2] * i1, oacc[nt][3] * i1);
    }
}

// ---------------- out = x + LayerNorm(t)*g + b (+ fp16 copy) ----------------
__global__ void __launch_bounds__(256)
add_ln_kernel(const float* __restrict__ x, const float* __restrict__ t,
              const float* __restrict__ gw, const float* __restrict__ bw,
              float* __restrict__ out, __half* __restrict__ outh)
{
    __shared__ float r1[8], r2[8];
    const int base = blockIdx.x * 1024;
    const int tid = threadIdx.x;
    float4 tv = *(const float4*)(t + base + tid * 4);
    float s = tv.x + tv.y + tv.z + tv.w;
    float q = tv.x * tv.x + tv.y * tv.y + tv.z * tv.z + tv.w * tv.w;
#pragma unroll
    for (int o = 16; o; o >>= 1) {
        s += __shfl_xor_sync(0xffffffffu, s, o);
        q += __shfl_xor_sync(0xffffffffu, q, o);
    }
    if ((tid & 31) == 0) { r1[tid >> 5] = s; r2[tid >> 5] = q; }
    __syncthreads();
    if (tid < 32) {
        float ss = (tid < 8) ? r1[tid] : 0.f;
        float qq = (tid < 8) ? r2[tid] : 0.f;
#pragma unroll
        for (int o = 4; o; o >>= 1) {
            ss += __shfl_xor_sync(0xffffffffu, ss, o);
            qq += __shfl_xor_sync(0xffffffffu, qq, o);
        }
        if (tid == 0) { r1[0] = ss; r2[0] = qq; }
    }
    __syncthreads();
    const float mean = r1[0] * (1.f / 1024.f);
    const float var  = r2[0] * (1.f / 1024.f) - mean * mean;
    const float rstd = rsqrtf(var + 1e-5f);

    float4 xv = *(const float4*)(x + base + tid * 4);
    float4 gv = *(const float4*)(gw + tid * 4);
    float4 bv = *(const float4*)(bw + tid * 4);
    float4 o;
    o.x = xv.x + (tv.x - mean) * rstd * gv.x + bv.x;
    o.y = xv.y + (tv.y - mean) * rstd * gv.y + bv.y;
    o.z = xv.z + (tv.z - mean) * rstd * gv.z + bv.z;
    o.w = xv.w + (tv.w - mean) * rstd * gv.w + bv.w;
    *(float4*)(out + base + tid * 4) = o;
    if (outh) {
        __half2* oh = (__half2*)(outh + base + tid * 4);
        oh[0] = __floats2half2_rn(o.x, o.y);
        oh[1] = __floats2half2_rn(o.z, o.w);
    }
}

// ---------------- launch ----------------
template<class T>
static T* sym_addr(const void* s) {
    void* p = nullptr;
    cudaGetSymbolAddress(&p, s);
    return (T*)p;
}

extern "C" void kernel_launch(void* const* d_in, const int* in_sizes, int n_in,
                              void* d_out, int out_size)
{
    (void)in_sizes; (void)n_in; (void)out_size;
    const float* x   = (const float*)d_in[0];
    const float* Wq  = (const float*)d_in[1];
    const float* bq  = (const float*)d_in[2];
    const float* Wk  = (const float*)d_in[3];
    const float* bk  = (const float*)d_in[4];
    const float* Wv  = (const float*)d_in[5];
    const float* bv  = (const float*)d_in[6];
    const float* Wo  = (const float*)d_in[7];
    const float* bo  = (const float*)d_in[8];
    const float* W1  = (const float*)d_in[9];
    const float* b1  = (const float*)d_in[10];
    const float* W2  = (const float*)d_in[11];
    const float* b2  = (const float*)d_in[12];
    const float* g1  = (const float*)d_in[13];
    const float* be1 = (const float*)d_in[14];
    const float* g2  = (const float*)d_in[15];
    const float* be2 = (const float*)d_in[16];
    float* out = (float*)d_out;

    __half* xh   = sym_addr<__half>(g_xh);
    __half* wqkv = sym_addr<__half>(g_wqkv);
    __half* wo   = sym_addr<__half>(g_wo);
    __half* w1   = sym_addr<__half>(g_w1);
    __half* w2   = sym_addr<__half>(g_w2);
    __half* q    = sym_addr<__half>(g_q);
    __half* k    = sym_addr<__half>(g_k);
    __half* vt   = sym_addr<__half>(g_vt);
    __half* oc   = sym_addr<__half>(g_oc);
    float*  at   = sym_addr<float>(g_at);
    float*  x1   = sym_addr<float>(g_x1);
    __half* x1h  = sym_addr<__half>(g_x1h);
    __half* ff   = sym_addr<__half>(g_ff);
    float*  ps   = sym_addr<float>(g_ps);

    const int FSM = FL_SMH * 2;
    cudaFuncSetAttribute(gemm_h2<0>, cudaFuncAttributeMaxDynamicSharedMemorySize, G2SM);
    cudaFuncSetAttribute(gemm_h2<1>, cudaFuncAttributeMaxDynamicSharedMemorySize, G2SM);
    cudaFuncSetAttribute(gemm_h2<2>, cudaFuncAttributeMaxDynamicSharedMemorySize, G2SM);
    cudaFuncSetAttribute(flash_h,    cudaFuncAttributeMaxDynamicSharedMemorySize, FSM);

    const dim3 blk(256);
    const dim3 tb(32, 8);

    // conversions (weights -> [N,K] fp16; QKV packed into one [3072,1024] buffer)
    cvt_half<<<4096, blk>>>(x, xh, 4194304);
    trh_qkv<<<dim3(2, 32, 16), tb>>>(Wq, wqkv);
    trh_qkv<<<dim3(2, 32, 16), tb>>>(Wk, wqkv + 1024 * 1024);
    trh_qkv<<<dim3(2, 32, 16), tb>>>(Wv, wqkv + 2 * 1024 * 1024);
    trh<<<dim3(32, 32),  tb>>>(Wo, wo, 1024, 1024);
    trh<<<dim3(128, 32), tb>>>(W1, w1, 1024, 4096);
    trh<<<dim3(32, 128), tb>>>(W2, w2, 4096, 1024);

    // fused QKV projection (q scaled by 1/8 in epilogue)
    gemm_h2<1><<<dim3(24, 32), blk, G2SM>>>(xh, wqkv, bq, bk, bv,
                                            q, k, vt, 4096, 3072, 1024, 0);

    // fused attention
    flash_h<<<dim3(8, 64), blk, FSM>>>(q, k, vt, oc);

    // output projection + LN
    gemm_h2<2><<<dim3(8, 32), blk, G2SM>>>(oc, wo, bo, nullptr, nullptr,
                                           at, nullptr, nullptr, 4096, 1024, 1024, 0);
    add_ln_kernel<<<4096, blk>>>(x, at, g1, be1, x1, x1h);

    // FFN
    gemm_h2<0><<<dim3(32, 32), blk, G2SM>>>(x1h, w1, b1, nullptr, nullptr,
                                            ff, nullptr, nullptr, 4096, 4096, 1024, 1);
    gemm_h2<2><<<dim3(8, 32), blk, G2SM>>>(ff, w2, b2, nullptr, nullptr,
                                           ps, nullptr, nullptr, 4096, 1024, 4096, 0);

    add_ln_kernel<<<4096, blk>>>(x1, ps, g2, be2, out, nullptr);
}

// round 6
// speedup vs baseline: 3.8755x; 1.0274x over previous
#include <cuda_runtime.h>
#include <cuda_fp16.h>

#define BB 4
#define SS 1024
#define DD 1024
#define HH 16
#define DKC 64
#define DFF 4096

// ---------------- scratch ----------------
__device__ __half g_xh  [BB*SS*DD];         // x fp16 [M,K]
__device__ __half g_wqkv[3*DD*DD];          // packed [3072 n][1024 k] fp16 (q,k,v)
__device__ __half g_wo  [DD*DD];            // [N,K] fp16
__device__ __half g_w1  [DFF*DD];           // [4096,1024]
__device__ __half g_w2  [DD*DFF];           // [1024,4096]
__device__ __half g_q   [BB*HH*SS*DKC];     // [z][s][dk]
__device__ __half g_k   [BB*HH*SS*DKC];
__device__ __half g_vt  [BB*HH*DKC*SS];     // [z][dk][s]
__device__ __half g_oc  [BB*SS*DD];         // attn concat fp16
__device__ float  g_at  [BB*SS*DD];
__device__ float  g_x1  [BB*SS*DD];
__device__ __half g_x1h [BB*SS*DD];
__device__ __half g_ff  [BB*SS*DFF];
__device__ float  g_ps  [BB*SS*DD];

// ---------------- asm helpers ----------------
__device__ __forceinline__ void cp16(unsigned dst, const void* src) {
    asm volatile("cp.async.cg.shared.global [%0], [%1], 16;" :: "r"(dst), "l"(src));
}
__device__ __forceinline__ void cp_commit() { asm volatile("cp.async.commit_group;" ::: "memory"); }
__device__ __forceinline__ void cp_wait0()  { asm volatile("cp.async.wait_group 0;" ::: "memory"); }
__device__ __forceinline__ void cp_wait1()  { asm volatile("cp.async.wait_group 1;" ::: "memory"); }

__device__ __forceinline__ void ldm_x4(unsigned& r0, unsigned& r1, unsigned& r2, unsigned& r3, unsigned addr) {
    asm volatile("ldmatrix.sync.aligned.m8n8.x4.shared.b16 {%0,%1,%2,%3}, [%4];"
                 : "=r"(r0), "=r"(r1), "=r"(r2), "=r"(r3) : "r"(addr));
}
__device__ __forceinline__ void stm_x2(unsigned addr, unsigned r0, unsigned r1) {
    asm volatile("stmatrix.sync.aligned.m8n8.x2.shared.b16 [%0], {%1,%2};"
                 :: "r"(addr), "r"(r0), "r"(r1) : "memory");
}
__device__ __forceinline__ void mma16(float* c, const unsigned* a, const unsigned* b) {
    asm volatile(
        "mma.sync.aligned.m16n8k16.row.col.f32.f16.f16.f32 "
        "{%0,%1,%2,%3},{%4,%5,%6,%7},{%8,%9},{%0,%1,%2,%3};"
        : "+f"(c[0]), "+f"(c[1]), "+f"(c[2]), "+f"(c[3])
        : "r"(a[0]), "r"(a[1]), "r"(a[2]), "r"(a[3]), "r"(b[0]), "r"(b[1]));
}

// ---------------- fused conversion kernel ----------------
// blocks [0,4096): x -> xh           (fp32 -> fp16 copy)
// blocks [4096,7168): Wq/Wk/Wv [H,D,DK] -> wqkv [3072 n][1024 k]
// blocks [7168,8192): Wo transpose   [1024,1024] -> [N,K]
// blocks [8192,12288): W1 transpose  [1024,4096] -> [4096,1024]
// blocks [12288,16384): W2 transpose [4096,1024] -> [1024,4096]
__global__ void __launch_bounds__(256)
cvt_all(const float* __restrict__ x,
        const float* __restrict__ Wq, const float* __restrict__ Wk,
        const float* __restrict__ Wv, const float* __restrict__ Wo,
        const float* __restrict__ W1, const float* __restrict__ W2,
        __half* __restrict__ xh, __half* __restrict__ wqkv,
        __half* __restrict__ wo, __half* __restrict__ w1, __half* __restrict__ w2)
{
    __shared__ float t[32][33];
    const int tx = threadIdx.x, ty = threadIdx.y;
    const int tid = ty * 32 + tx;
    int b = blockIdx.x;

    if (b < 4096) {
        const int i = (b * 256 + tid) * 4;
        float4 v = *(const float4*)(x + i);
        __half2* o = (__half2*)(xh + i);
        o[0] = __floats2half2_rn(v.x, v.y);
        o[1] = __floats2half2_rn(v.z, v.w);
        return;
    }
    b -= 4096;
    if (b < 3072) {   // QKV weight transpose-pack
        const int w = b >> 10, r = b & 1023;
        const float* src = (w == 0) ? Wq : (w == 1 ? Wk : Wv);
        __half* dst = wqkv + w * 1048576;
        const int h = r >> 6, rem = r & 63;
        const int d0 = (rem >> 1) * 32, dk0 = (rem & 1) * 32;
        const float* ip = src + h * 65536;
#pragma unroll
        for (int j = 0; j < 4; j++)
            t[ty + 8 * j][tx] = ip[(d0 + ty + 8 * j) * 64 + dk0 + tx];
        __syncthreads();
#pragma unroll
        for (int j = 0; j < 4; j++)
            dst[(h * 64 + dk0 + ty + 8 * j) * 1024 + d0 + tx] = __float2half(t[tx][ty + 8 * j]);
        return;
    }
    b -= 3072;
    const float* src; __half* dst; int K, N, n0, k0;
    if (b < 1024)        { src = Wo; dst = wo; K = 1024; N = 1024; n0 = (b & 31) * 32; k0 = (b >> 5) * 32; }
    else if (b < 5120)   { b -= 1024; src = W1; dst = w1; K = 1024; N = 4096; n0 = (b & 127) * 32; k0 = (b >> 7) * 32; }
    else                 { b -= 5120; src = W2; dst = w2; K = 4096; N = 1024; n0 = (b & 31) * 32; k0 = (b >> 5) * 32; }
#pragma unroll
    for (int j = 0; j < 4; j++)
        t[ty + 8 * j][tx] = src[(k0 + ty + 8 * j) * N + n0 + tx];
    __syncthreads();
#pragma unroll
    for (int j = 0; j < 4; j++)
        dst[(n0 + ty + 8 * j) * K + k0 + tx] = __float2half(t[tx][ty + 8 * j]);
}

// ---------------- fp16 GEMM (unchanged from R5, validated) ----------------
#define STG_B 32768
#define G2SM  (3*STG_B)
__device__ __forceinline__ unsigned tswz(int row, int kbyte) {
    return (unsigned)(row * 128 + ((kbyte ^ ((row & 7) << 4)) & 127) + (kbyte & ~127));
}

template<int EPI>
__global__ void __launch_bounds__(256, 2)
gemm_h2(const __half* __restrict__ A, const __half* __restrict__ Bt,
        const float* __restrict__ b0p, const float* __restrict__ b1p,
        const float* __restrict__ b2p, void* __restrict__ C0,
        void* __restrict__ C1, void* __restrict__ C2,
        int M, int N, int K, int relu)
{
    extern __shared__ char dsm[];
    const unsigned smB = (unsigned)__cvta_generic_to_shared(dsm);

    const int tid = threadIdx.x, lane = tid & 31, wid = tid >> 5;
    const int wm = wid & 1, wn = wid >> 1;
    const int Rb = blockIdx.y * 128;
    const int Nb = blockIdx.x * 128;
    const int nS = K >> 6;

    const int crow = tid >> 3, ckc = (tid & 7) * 16;
    const int lr = lane & 15, lhb = ((lane >> 4) << 4);

    auto issue = [&](int it) {
        const unsigned sA = smB + (it % 3) * STG_B;
        const unsigned sB = sA + 16384;
        const __half* Ap = A + (Rb + crow) * K + it * 64 + ckc / 2;
        const __half* Bp = Bt + (Nb + crow) * K + it * 64 + ckc / 2;
#pragma unroll
        for (int i = 0; i < 4; i++)
            cp16(sA + tswz(crow + 32 * i, ckc), Ap + 32 * i * K);
#pragma unroll
        for (int i = 0; i < 4; i++)
            cp16(sB + tswz(crow + 32 * i, ckc), Bp + 32 * i * K);
    };

    float acc[4][4][4];
#pragma unroll
    for (int i = 0; i < 4; i++)
#pragma unroll
        for (int j = 0; j < 4; j++)
#pragma unroll
            for (int r = 0; r < 4; r++) acc[i][j][r] = 0.f;

    issue(0); cp_commit();
    issue(1); cp_commit();

    for (int it = 0; it < nS; it++) {
        cp_wait1();
        __syncthreads();
        if (it + 2 < nS) issue(it + 2);
        cp_commit();

        const unsigned sA = smB + (it % 3) * STG_B;
        const unsigned sB = sA + 16384;
#pragma unroll
        for (int s = 0; s < 4; s++) {
            const int kb = s * 32;
            unsigned af[4][4], bf[2][4];
#pragma unroll
            for (int mt = 0; mt < 4; mt++)
                ldm_x4(af[mt][0], af[mt][1], af[mt][2], af[mt][3],
                       sA + tswz(wm * 64 + mt * 16 + lr, kb + lhb));
#pragma unroll
            for (int nt2 = 0; nt2 < 2; nt2++)
                ldm_x4(bf[nt2][0], bf[nt2][1], bf[nt2][2], bf[nt2][3],
                       sB + tswz(wn * 32 + nt2 * 16 + lr, kb + lhb));
#pragma unroll
            for (int mt = 0; mt < 4; mt++)
#pragma unroll
                for (int nt = 0; nt < 4; nt++) {
                    unsigned b[2] = { bf[nt >> 1][nt & 1], bf[nt >> 1][(nt & 1) + 2] };
                    mma16(acc[mt][nt], af[mt], b);
                }
        }
    }

    const int tq = lane & 3, gq = lane >> 2;
#pragma unroll
    for (int mt = 0; mt < 4; mt++) {
#pragma unroll
        for (int nt = 0; nt < 4; nt++) {
            const int m0 = Rb + wm * 64 + mt * 16 + gq;
            const int n0 = Nb + wn * 32 + nt * 8 + tq * 2;
            float bb0 = 0.f, bb1 = 0.f, alpha = 1.f;
            int seg = 0, nn = n0;
            if (EPI == 1) {
                seg = n0 >> 10; nn = n0 & 1023;
                const float* bp = seg == 0 ? b0p : (seg == 1 ? b1p : b2p);
                const int hh = nn >> 6, dk = nn & 63;
                bb0 = bp[hh * 64 + dk]; bb1 = bp[hh * 64 + dk + 1];
                if (seg == 0) alpha = 0.125f;
            } else if (b0p) {
                bb0 = b0p[n0]; bb1 = b0p[n0 + 1];
            }
#pragma unroll
            for (int half = 0; half < 2; half++) {
                const int m = m0 + half * 8;
                float v0 = (acc[mt][nt][half * 2 + 0] + bb0) * alpha;
                float v1 = (acc[mt][nt][half * 2 + 1] + bb1) * alpha;
                if (relu) { v0 = fmaxf(v0, 0.f); v1 = fmaxf(v1, 0.f); }
                if (EPI == 0) {
                    *(__half2*)((__half*)C0 + m * N + n0) = __floats2half2_rn(v0, v1);
                } else if (EPI == 2) {
                    *(float2*)((float*)C0 + m * N + n0) = make_float2(v0, v1);
                } else {
                    const int b = m >> 10, s = m & 1023;
                    const int hh = nn >> 6, dk = nn & 63;
                    if (seg == 0) {
                        *(__half2*)((__half*)C0 + ((b * 16 + hh) * 1024 + s) * 64 + dk) =
                            __floats2half2_rn(v0, v1);
                    } else if (seg == 1) {
                        *(__half2*)((__half*)C1 + ((b * 16 + hh) * 1024 + s) * 64 + dk) =
                            __floats2half2_rn(v0, v1);
                    } else {
                        __half* vp = (__half*)C2 + (b * 16 + hh) * 65536 + s;
                        vp[dk * 1024]       = __float2half(v0);
                        vp[(dk + 1) * 1024] = __float2half(v1);
                    }
                }
            }
        }
    }
}

// ---------------- fp16 flash attention v2 ----------------
// x4 operand loads, V double-buffered, K/V prefetch overlapped with softmax+PV.
#define QST 72
#define VST 136
#define OFF_K  (128*QST)
#define OFF_V0 (OFF_K + 128*QST)
#define VBUF   (64*VST)
#define OFF_P  (OFF_V0 + 2*VBUF)
#define FL_SMH (OFF_P + 128*VST)     // 53248 halfs = 106496 B
__global__ void __launch_bounds__(256, 2)
flash_h(const __half* __restrict__ Qg, const __half* __restrict__ Kg,
        const __half* __restrict__ Vg, __half* __restrict__ O)
{
    extern __shared__ __half sm[];
    const unsigned smB = (unsigned)__cvta_generic_to_shared(sm);
    const unsigned sQ = smB, sK = smB + OFF_K * 2;
    const unsigned sV0 = smB + OFF_V0 * 2, sP = smB + OFF_P * 2;

    const int tid = threadIdx.x, lane = tid & 31, wid = tid >> 5;
    const int tq = lane & 3, gq = lane >> 2;
    const int lr = lane & 15, lh = (lane >> 4) << 3;
    const int z = blockIdx.y, qt = blockIdx.x;

    const __half* Qp = Qg + (z * 1024 + qt * 128) * 64;
    const __half* Kp = Kg + z * 1024 * 64;
    const __half* Vp = Vg + z * 65536;

    auto stageK = [&](int kt) {
#pragma unroll
        for (int i = 0; i < 4; i++) {
            const int c = tid + 256 * i;
            const int row = c >> 3, cc = (c & 7) * 8;
            cp16(sK + (row * QST + cc) * 2, Kp + (kt * 128 + row) * 64 + cc);
        }
    };
    auto stageV = [&](int kt, unsigned dst) {
#pragma unroll
        for (int i = 0; i < 4; i++) {
            const int c = tid + 256 * i;
            const int row = c >> 4, cc = (c & 15) * 8;
            cp16(dst + (row * VST + cc) * 2, Vp + row * 1024 + kt * 128 + cc);
        }
    };

    // prologue: Q + K0 + V0
#pragma unroll
    for (int i = 0; i < 4; i++) {
        const int c = tid + 256 * i;
        const int row = c >> 3, cc = (c & 7) * 8;
        cp16(sQ + (row * QST + cc) * 2, Qp + row * 64 + cc);
    }
    stageK(0);
    stageV(0, sV0);
    cp_commit(); cp_wait0();
    __syncthreads();

    float oacc[8][4];
#pragma unroll
    for (int i = 0; i < 8; i++)
#pragma unroll
        for (int j = 0; j < 4; j++) oacc[i][j] = 0.f;
    float mrow0 = -1e30f, mrow1 = -1e30f, lrow0 = 0.f, lrow1 = 0.f;

    const unsigned aQbase = sQ + ((wid * 16 + lr) * QST + lh) * 2;
    const unsigned aPbase = sP + ((wid * 16 + lr) * VST + lh) * 2;

    for (int kt = 0; kt < 8; kt++) {
        const unsigned sV = sV0 + (kt & 1) * (VBUF * 2);

        // ---- S = Q @ K^T ----
        float sacc[16][4];
#pragma unroll
        for (int i = 0; i < 16; i++)
#pragma unroll
            for (int j = 0; j < 4; j++) sacc[i][j] = 0.f;
#pragma unroll
        for (int k16 = 0; k16 < 4; k16++) {
            const int kb = k16 * 32;   // bytes
            unsigned a[4];
            ldm_x4(a[0], a[1], a[2], a[3], aQbase + kb);
#pragma unroll
            for (int ntp = 0; ntp < 8; ntp++) {
                unsigned t0, t1, t2, t3;
                ldm_x4(t0, t1, t2, t3, sK + ((ntp * 16 + lr) * QST) * 2 + lh * 2 + kb);
                unsigned b0[2] = { t0, t2 }, b1[2] = { t1, t3 };
                mma16(sacc[2 * ntp],     a, b0);
                mma16(sacc[2 * ntp + 1], a, b1);
            }
        }

        // all warps done reading sK -> prefetch next K/V under softmax+PV
        __syncthreads();
        if (kt < 7) {
            stageK(kt + 1);
            stageV(kt + 1, sV0 + ((kt + 1) & 1) * (VBUF * 2));
            cp_commit();
        }

        // ---- online softmax ----
        float m0 = -1e30f, m1 = -1e30f;
#pragma unroll
        for (int nt = 0; nt < 16; nt++) {
            m0 = fmaxf(m0, fmaxf(sacc[nt][0], sacc[nt][1]));
            m1 = fmaxf(m1, fmaxf(sacc[nt][2], sacc[nt][3]));
        }
        m0 = fmaxf(m0, __shfl_xor_sync(0xffffffffu, m0, 1));
        m0 = fmaxf(m0, __shfl_xor_sync(0xffffffffu, m0, 2));
        m1 = fmaxf(m1, __shfl_xor_sync(0xffffffffu, m1, 1));
        m1 = fmaxf(m1, __shfl_xor_sync(0xffffffffu, m1, 2));
        const float mn0 = fmaxf(mrow0, m0), mn1 = fmaxf(mrow1, m1);
        const float sc0 = __expf(mrow0 - mn0), sc1 = __expf(mrow1 - mn1);

        float rs0 = 0.f, rs1 = 0.f;
        const unsigned pAddr = sP + ((wid * 16 + lr) * VST) * 2;
#pragma unroll
        for (int nt = 0; nt < 16; nt++) {
            const float p0 = __expf(sacc[nt][0] - mn0);
            const float p1 = __expf(sacc[nt][1] - mn0);
            const float p2 = __expf(sacc[nt][2] - mn1);
            const float p3 = __expf(sacc[nt][3] - mn1);
            rs0 += p0 + p1; rs1 += p2 + p3;
            __half2 h01 = __floats2half2_rn(p0, p1);
            __half2 h23 = __floats2half2_rn(p2, p3);
            stm_x2(pAddr + nt * 16, *(unsigned*)&h01, *(unsigned*)&h23);
        }
        rs0 += __shfl_xor_sync(0xffffffffu, rs0, 1);
        rs0 += __shfl_xor_sync(0xffffffffu, rs0, 2);
        rs1 += __shfl_xor_sync(0xffffffffu, rs1, 1);
        rs1 += __shfl_xor_sync(0xffffffffu, rs1, 2);
        lrow0 = lrow0 * sc0 + rs0;
        lrow1 = lrow1 * sc1 + rs1;
        mrow0 = mn0; mrow1 = mn1;
#pragma unroll
        for (int nt = 0; nt < 8; nt++) {
            oacc[nt][0] *= sc0; oacc[nt][1] *= sc0;
            oacc[nt][2] *= sc1; oacc[nt][3] *= sc1;
        }
        __syncwarp();

        // ---- O += P @ V ----
#pragma unroll
        for (int k16 = 0; k16 < 8; k16++) {
            const int kb = k16 * 32;
            unsigned a[4];
            ldm_x4(a[0], a[1], a[2], a[3], aPbase + kb);
#pragma unroll
            for (int ntp = 0; ntp < 4; ntp++) {
                unsigned t0, t1, t2, t3;
                ldm_x4(t0, t1, t2, t3, sV + ((ntp * 16 + lr) * VST) * 2 + lh * 2 + kb);
                unsigned b0[2] = { t0, t2 }, b1[2] = { t1, t3 };
                mma16(oacc[2 * ntp],     a, b0);
                mma16(oacc[2 * ntp + 1], a, b1);
            }
        }

        if (kt < 7) {
            cp_wait0();
            __syncthreads();
        }
    }

    const float i0 = 1.f / lrow0, i1 = 1.f / lrow1;
    const int b = z >> 4, h = z & 15;
    const int s0 = qt * 128 + wid * 16 + gq;
#pragma unroll
    for (int nt = 0; nt < 8; nt++) {
        const int col = h * 64 + nt * 8 + 2 * tq;
        *(__half2*)&O[(b * 1024 + s0) * 1024 + col] =
            __floats2half2_rn(oacc[nt][0] * i0, oacc[nt][1] * i0);
        *(__half2*)&O[(b * 1024 + s0 + 8) * 1024 + col] =
            __floats2half2_rn(oacc[nt][2] * i1, oacc[nt][3] * i1);
    }
}

// ---------------- out = x + LayerNorm(t)*g + b (+ fp16 copy) ----------------
__global__ void __launch_bounds__(256)
add_ln_kernel(const float* __restrict__ x, const float* __restrict__ t,
              const float* __restrict__ gw, const float* __restrict__ bw,
              float* __restrict__ out, __half* __restrict__ outh)
{
    __shared__ float r1[8], r2[8];
    const int base = blockIdx.x * 1024;
    const int tid = threadIdx.x;
    float4 tv = *(const float4*)(t + base + tid * 4);
    float s = tv.x + tv.y + tv.z + tv.w;
    float q = tv.x * tv.x + tv.y * tv.y + tv.z * tv.z + tv.w * tv.w;
#pragma unroll
    for (int o = 16; o; o >>= 1) {
        s += __shfl_xor_sync(0xffffffffu, s, o);
        q += __shfl_xor_sync(0xffffffffu, q, o);
    }
    if ((tid & 31) == 0) { r1[tid >> 5] = s; r2[tid >> 5] = q; }
    __syncthreads();
    if (tid < 32) {
        float ss = (tid < 8) ? r1[tid] : 0.f;
        float qq = (tid < 8) ? r2[tid] : 0.f;
#pragma unroll
        for (int o = 4; o; o >>= 1) {
            ss += __shfl_xor_sync(0xffffffffu, ss, o);
            qq += __shfl_xor_sync(0xffffffffu, qq, o);
        }
        if (tid == 0) { r1[0] = ss; r2[0] = qq; }
    }
    __syncthreads();
    const float mean = r1[0] * (1.f / 1024.f);
    const float var  = r2[0] * (1.f / 1024.f) - mean * mean;
    const float rstd = rsqrtf(var + 1e-5f);

    float4 xv = *(const float4*)(x + base + tid * 4);
    float4 gv = *(const float4*)(gw + tid * 4);
    float4 bv = *(const float4*)(bw + tid * 4);
    float4 o;
    o.x = xv.x + (tv.x - mean) * rstd * gv.x + bv.x;
    o.y = xv.y + (tv.y - mean) * rstd * gv.y + bv.y;
    o.z = xv.z + (tv.z - mean) * rstd * gv.z + bv.z;
    o.w = xv.w + (tv.w - mean) * rstd * gv.w + bv.w;
    *(float4*)(out + base + tid * 4) = o;
    if (outh) {
        __half2* oh = (__half2*)(outh + base + tid * 4);
        oh[0] = __floats2half2_rn(o.x, o.y);
        oh[1] = __floats2half2_rn(o.z, o.w);
    }
}

// ---------------- launch ----------------
template<class T>
static T* sym_addr(const void* s) {
    void* p = nullptr;
    cudaGetSymbolAddress(&p, s);
    return (T*)p;
}

extern "C" void kernel_launch(void* const* d_in, const int* in_sizes, int n_in,
                              void* d_out, int out_size)
{
    (void)in_sizes; (void)n_in; (void)out_size;
    const float* x   = (const float*)d_in[0];
    const float* Wq  = (const float*)d_in[1];
    const float* bq  = (const float*)d_in[2];
    const float* Wk  = (const float*)d_in[3];
    const float* bk  = (const float*)d_in[4];
    const float* Wv  = (const float*)d_in[5];
    const float* bv  = (const float*)d_in[6];
    const float* Wo  = (const float*)d_in[7];
    const float* bo  = (const float*)d_in[8];
    const float* W1  = (const float*)d_in[9];
    const float* b1  = (const float*)d_in[10];
    const float* W2  = (const float*)d_in[11];
    const float* b2  = (const float*)d_in[12];
    const float* g1  = (const float*)d_in[13];
    const float* be1 = (const float*)d_in[14];
    const float* g2  = (const float*)d_in[15];
    const float* be2 = (const float*)d_in[16];
    float* out = (float*)d_out;

    __half* xh   = sym_addr<__half>(g_xh);
    __half* wqkv = sym_addr<__half>(g_wqkv);
    __half* wo   = sym_addr<__half>(g_wo);
    __half* w1   = sym_addr<__half>(g_w1);
    __half* w2   = sym_addr<__half>(g_w2);
    __half* q    = sym_addr<__half>(g_q);
    __half* k    = sym_addr<__half>(g_k);
    __half* vt   = sym_addr<__half>(g_vt);
    __half* oc   = sym_addr<__half>(g_oc);
    float*  at   = sym_addr<float>(g_at);
    float*  x1   = sym_addr<float>(g_x1);
    __half* x1h  = sym_addr<__half>(g_x1h);
    __half* ff   = sym_addr<__half>(g_ff);
    float*  ps   = sym_addr<float>(g_ps);

    const int FSM = FL_SMH * 2;
    cudaFuncSetAttribute(gemm_h2<0>, cudaFuncAttributeMaxDynamicSharedMemorySize, G2SM);
    cudaFuncSetAttribute(gemm_h2<1>, cudaFuncAttributeMaxDynamicSharedMemorySize, G2SM);
    cudaFuncSetAttribute(gemm_h2<2>, cudaFuncAttributeMaxDynamicSharedMemorySize, G2SM);
    cudaFuncSetAttribute(flash_h,    cudaFuncAttributeMaxDynamicSharedMemorySize, FSM);

    const dim3 blk(256);

    // single fused conversion pass
    cvt_all<<<16384, dim3(32, 8)>>>(x, Wq, Wk, Wv, Wo, W1, W2,
                                    xh, wqkv, wo, w1, w2);

    // fused QKV projection (q scaled by 1/8 in epilogue)
    gemm_h2<1><<<dim3(24, 32), blk, G2SM>>>(xh, wqkv, bq, bk, bv,
                                            q, k, vt, 4096, 3072, 1024, 0);

    // fused attention
    flash_h<<<dim3(8, 64), blk, FSM>>>(q, k, vt, oc);

    // output projection + LN
    gemm_h2<2><<<dim3(8, 32), blk, G2SM>>>(oc, wo, bo, nullptr, nullptr,
                                           at, nullptr, nullptr, 4096, 1024, 1024, 0);
    add_ln_kernel<<<4096, blk>>>(x, at, g1, be1, x1, x1h);

    // FFN
    gemm_h2<0><<<dim3(32, 32), blk, G2SM>>>(x1h, w1, b1, nullptr, nullptr,
                                            ff, nullptr, nullptr, 4096, 4096, 1024, 1);
    gemm_h2<2><<<dim3(8, 32), blk, G2SM>>>(ff, w2, b2, nullptr, nullptr,
                                           ps, nullptr, nullptr, 4096, 1024, 4096, 0);

    add_ln_kernel<<<4096, blk>>>(x1, ps, g2, be2, out, nullptr);
}

// round 7
// speedup vs baseline: 3.9671x; 1.0236x over previous
#include <cuda_runtime.h>
#include <cuda_fp16.h>

#define BB 4
#define SS 1024
#define DD 1024
#define HH 16
#define DKC 64
#define DFF 4096

// ---------------- scratch ----------------
__device__ __half g_xh  [BB*SS*DD];
__device__ __half g_wqkv[3*DD*DD];          // packed [3072 n][1024 k]
__device__ __half g_wo  [DD*DD];
__device__ __half g_w1  [DFF*DD];
__device__ __half g_w2  [DD*DFF];
__device__ __half g_q   [BB*HH*SS*DKC];     // [z][s][dk]
__device__ __half g_k   [BB*HH*SS*DKC];
__device__ __half g_v   [BB*HH*SS*DKC];     // [z][s][dk]  (no transpose)
__device__ __half g_oc  [BB*SS*DD];
__device__ float  g_at  [BB*SS*DD];
__device__ float  g_x1  [BB*SS*DD];
__device__ __half g_x1h [BB*SS*DD];
__device__ __half g_ff  [BB*SS*DFF];
__device__ float  g_ps  [BB*SS*DD];

// ---------------- asm helpers ----------------
__device__ __forceinline__ void cp16(unsigned dst, const void* src) {
    asm volatile("cp.async.cg.shared.global [%0], [%1], 16;" :: "r"(dst), "l"(src));
}
__device__ __forceinline__ void cp_commit() { asm volatile("cp.async.commit_group;" ::: "memory"); }
__device__ __forceinline__ void cp_wait0()  { asm volatile("cp.async.wait_group 0;" ::: "memory"); }
__device__ __forceinline__ void cp_wait1()  { asm volatile("cp.async.wait_group 1;" ::: "memory"); }

__device__ __forceinline__ void ldm_x4(unsigned& r0, unsigned& r1, unsigned& r2, unsigned& r3, unsigned addr) {
    asm volatile("ldmatrix.sync.aligned.m8n8.x4.shared.b16 {%0,%1,%2,%3}, [%4];"
                 : "=r"(r0), "=r"(r1), "=r"(r2), "=r"(r3) : "r"(addr));
}
__device__ __forceinline__ void ldm_x4t(unsigned& r0, unsigned& r1, unsigned& r2, unsigned& r3, unsigned addr) {
    asm volatile("ldmatrix.sync.aligned.m8n8.x4.trans.shared.b16 {%0,%1,%2,%3}, [%4];"
                 : "=r"(r0), "=r"(r1), "=r"(r2), "=r"(r3) : "r"(addr));
}
__device__ __forceinline__ void ldm_x2t(unsigned& r0, unsigned& r1, unsigned addr) {
    asm volatile("ldmatrix.sync.aligned.m8n8.x2.trans.shared.b16 {%0,%1}, [%2];"
                 : "=r"(r0), "=r"(r1) : "r"(addr));
}
__device__ __forceinline__ void stm_x2(unsigned addr, unsigned r0, unsigned r1) {
    asm volatile("stmatrix.sync.aligned.m8n8.x2.shared.b16 [%0], {%1,%2};"
                 :: "r"(addr), "r"(r0), "r"(r1) : "memory");
}
__device__ __forceinline__ void mma16(float* c, const unsigned* a, const unsigned* b) {
    asm volatile(
        "mma.sync.aligned.m16n8k16.row.col.f32.f16.f16.f32 "
        "{%0,%1,%2,%3},{%4,%5,%6,%7},{%8,%9},{%0,%1,%2,%3};"
        : "+f"(c[0]), "+f"(c[1]), "+f"(c[2]), "+f"(c[3])
        : "r"(a[0]), "r"(a[1]), "r"(a[2]), "r"(a[3]), "r"(b[0]), "r"(b[1]));
}
__device__ __forceinline__ unsigned ex2h2(unsigned x) {
    unsigned r;
    asm("ex2.approx.f16x2 %0, %1;" : "=r"(r) : "r"(x));
    return r;
}

// ---------------- fused conversion kernel ----------------
__global__ void __launch_bounds__(256)
cvt_all(const float* __restrict__ x,
        const float* __restrict__ Wq, const float* __restrict__ Wk,
        const float* __restrict__ Wv, const float* __restrict__ Wo,
        const float* __restrict__ W1, const float* __restrict__ W2,
        __half* __restrict__ xh, __half* __restrict__ wqkv,
        __half* __restrict__ wo, __half* __restrict__ w1, __half* __restrict__ w2)
{
    __shared__ float t[32][33];
    const int tx = threadIdx.x, ty = threadIdx.y;
    const int tid = ty * 32 + tx;
    int b = blockIdx.x;

    if (b < 4096) {
        const int i = (b * 256 + tid) * 4;
        float4 v = *(const float4*)(x + i);
        __half2* o = (__half2*)(xh + i);
        o[0] = __floats2half2_rn(v.x, v.y);
        o[1] = __floats2half2_rn(v.z, v.w);
        return;
    }
    b -= 4096;
    if (b < 3072) {
        const int w = b >> 10, r = b & 1023;
        const float* src = (w == 0) ? Wq : (w == 1 ? Wk : Wv);
        __half* dst = wqkv + w * 1048576;
        const int h = r >> 6, rem = r & 63;
        const int d0 = (rem >> 1) * 32, dk0 = (rem & 1) * 32;
        const float* ip = src + h * 65536;
#pragma unroll
        for (int j = 0; j < 4; j++)
            t[ty + 8 * j][tx] = ip[(d0 + ty + 8 * j) * 64 + dk0 + tx];
        __syncthreads();
#pragma unroll
        for (int j = 0; j < 4; j++)
            dst[(h * 64 + dk0 + ty + 8 * j) * 1024 + d0 + tx] = __float2half(t[tx][ty + 8 * j]);
        return;
    }
    b -= 3072;
    const float* src; __half* dst; int K, N, n0, k0;
    if (b < 1024)      { src = Wo; dst = wo; K = 1024; N = 1024; n0 = (b & 31) * 32; k0 = (b >> 5) * 32; }
    else if (b < 5120) { b -= 1024; src = W1; dst = w1; K = 1024; N = 4096; n0 = (b & 127) * 32; k0 = (b >> 7) * 32; }
    else               { b -= 5120; src = W2; dst = w2; K = 4096; N = 1024; n0 = (b & 31) * 32; k0 = (b >> 5) * 32; }
#pragma unroll
    for (int j = 0; j < 4; j++)
        t[ty + 8 * j][tx] = src[(k0 + ty + 8 * j) * N + n0 + tx];
    __syncthreads();
#pragma unroll
    for (int j = 0; j < 4; j++)
        dst[(n0 + ty + 8 * j) * K + k0 + tx] = __float2half(t[tx][ty + 8 * j]);
}

// ---------------- fp16 GEMM ----------------
// EPI 0: half out (+relu)  EPI 1: QKV via smem -> coalesced scatter  EPI 2: float out
#define STG_B 32768
#define G2SM  (3*STG_B)
__device__ __forceinline__ unsigned tswz(int row, int kbyte) {
    return (unsigned)(row * 128 + ((kbyte ^ ((row & 7) << 4)) & 127) + (kbyte & ~127));
}

template<int EPI>
__global__ void __launch_bounds__(256, 2)
gemm_h2(const __half* __restrict__ A, const __half* __restrict__ Bt,
        const float* __restrict__ b0p, const float* __restrict__ b1p,
        const float* __restrict__ b2p, void* __restrict__ C0,
        void* __restrict__ C1, void* __restrict__ C2,
        int M, int N, int K, int relu)
{
    extern __shared__ char dsm[];
    const unsigned smB = (unsigned)__cvta_generic_to_shared(dsm);

    const int tid = threadIdx.x, lane = tid & 31, wid = tid >> 5;
    const int wm = wid & 1, wn = wid >> 1;
    const int Rb = blockIdx.y * 128;
    const int Nb = blockIdx.x * 128;
    const int nS = K >> 6;

    const int crow = tid >> 3, ckc = (tid & 7) * 16;
    const int lr = lane & 15, lhb = ((lane >> 4) << 4);

    auto issue = [&](int it) {
        const unsigned sA = smB + (it % 3) * STG_B;
        const unsigned sB = sA + 16384;
        const __half* Ap = A + (Rb + crow) * K + it * 64 + ckc / 2;
        const __half* Bp = Bt + (Nb + crow) * K + it * 64 + ckc / 2;
#pragma unroll
        for (int i = 0; i < 4; i++)
            cp16(sA + tswz(crow + 32 * i, ckc), Ap + 32 * i * K);
#pragma unroll
        for (int i = 0; i < 4; i++)
            cp16(sB + tswz(crow + 32 * i, ckc), Bp + 32 * i * K);
    };

    float acc[4][4][4];
#pragma unroll
    for (int i = 0; i < 4; i++)
#pragma unroll
        for (int j = 0; j < 4; j++)
#pragma unroll
            for (int r = 0; r < 4; r++) acc[i][j][r] = 0.f;

    issue(0); cp_commit();
    issue(1); cp_commit();

    for (int it = 0; it < nS; it++) {
        cp_wait1();
        __syncthreads();
        if (it + 2 < nS) issue(it + 2);
        cp_commit();

        const unsigned sA = smB + (it % 3) * STG_B;
        const unsigned sB = sA + 16384;
#pragma unroll
        for (int s = 0; s < 4; s++) {
            const int kb = s * 32;
            unsigned af[4][4], bf[2][4];
#pragma unroll
            for (int mt = 0; mt < 4; mt++)
                ldm_x4(af[mt][0], af[mt][1], af[mt][2], af[mt][3],
                       sA + tswz(wm * 64 + mt * 16 + lr, kb + lhb));
#pragma unroll
            for (int nt2 = 0; nt2 < 2; nt2++)
                ldm_x4(bf[nt2][0], bf[nt2][1], bf[nt2][2], bf[nt2][3],
                       sB + tswz(wn * 32 + nt2 * 16 + lr, kb + lhb));
#pragma unroll
            for (int mt = 0; mt < 4; mt++)
#pragma unroll
                for (int nt = 0; nt < 4; nt++) {
                    unsigned b[2] = { bf[nt >> 1][nt & 1], bf[nt >> 1][(nt & 1) + 2] };
                    mma16(acc[mt][nt], af[mt], b);
                }
        }
    }

    const int tq = lane & 3, gq = lane >> 2;

    if (EPI == 1) {
        // stage into smem tile [128][136] halfs, then coalesced 16B scatter
        __syncthreads();
        __half* ep = (__half*)dsm;
#pragma unroll
        for (int mt = 0; mt < 4; mt++) {
#pragma unroll
            for (int nt = 0; nt < 4; nt++) {
                const int n0 = Nb + wn * 32 + nt * 8 + tq * 2;
                const int seg = n0 >> 10, nn = n0 & 1023;
                const float* bp = seg == 0 ? b0p : (seg == 1 ? b1p : b2p);
                const int hh = nn >> 6, dk = nn & 63;
                const float bb0 = bp[hh * 64 + dk], bb1 = bp[hh * 64 + dk + 1];
                const float alpha = (seg == 0) ? 0.125f : 1.f;
#pragma unroll
                for (int half = 0; half < 2; half++) {
                    const int r = wm * 64 + mt * 16 + gq + half * 8;
                    float v0 = (acc[mt][nt][half * 2 + 0] + bb0) * alpha;
                    float v1 = (acc[mt][nt][half * 2 + 1] + bb1) * alpha;
                    *(__half2*)&ep[r * 136 + wn * 32 + nt * 8 + tq * 2] =
                        __floats2half2_rn(v0, v1);
                }
            }
        }
        __syncthreads();
        const int bidx = Rb >> 10, sbase = Rb & 1023;
        for (int c = tid; c < 2048; c += 256) {
            const int r = c >> 4, s16 = c & 15;
            uint4 val = *(uint4*)&ep[r * 136 + s16 * 8];
            const int n = Nb + s16 * 8;
            const int seg = n >> 10, nn = n & 1023;
            const int hh = nn >> 6, dk = nn & 63;
            __half* dst = seg == 0 ? (__half*)C0 : (seg == 1 ? (__half*)C1 : (__half*)C2);
            *(uint4*)&dst[(((bidx * 16 + hh) << 10) + sbase + r) * 64 + dk] = val;
        }
        return;
    }

#pragma unroll
    for (int mt = 0; mt < 4; mt++) {
#pragma unroll
        for (int nt = 0; nt < 4; nt++) {
            const int m0 = Rb + wm * 64 + mt * 16 + gq;
            const int n0 = Nb + wn * 32 + nt * 8 + tq * 2;
            const float bb0 = b0p ? b0p[n0] : 0.f;
            const float bb1 = b0p ? b0p[n0 + 1] : 0.f;
#pragma unroll
            for (int half = 0; half < 2; half++) {
                const int m = m0 + half * 8;
                float v0 = acc[mt][nt][half * 2 + 0] + bb0;
                float v1 = acc[mt][nt][half * 2 + 1] + bb1;
                if (relu) { v0 = fmaxf(v0, 0.f); v1 = fmaxf(v1, 0.f); }
                if (EPI == 0)
                    *(__half2*)((__half*)C0 + m * N + n0) = __floats2half2_rn(v0, v1);
                else
                    *(float2*)((float*)C0 + m * N + n0) = make_float2(v0, v1);
            }
        }
    }
}

// ---------------- fp16 flash attention v3 ----------------
// V stored [z][s][dk]; PV uses trans-ldmatrix. Row-sum l via ones-column in V
// padding (col 64). exp via ex2.approx.f16x2.
#define QST 72
#define PST 136
#define OFF_K  (128*QST)
#define OFF_V0 (2*128*QST)
#define VBUF   (128*QST)
#define OFF_P  (4*128*QST)
#define FL_SMH (OFF_P + 128*PST)     // 54272 halfs = 108544 B
__global__ void __launch_bounds__(256, 2)
flash_h(const __half* __restrict__ Qg, const __half* __restrict__ Kg,
        const __half* __restrict__ Vg, __half* __restrict__ O)
{
    extern __shared__ __half sm[];
    const unsigned smB = (unsigned)__cvta_generic_to_shared(sm);
    const unsigned sQ = smB, sK = smB + OFF_K * 2;
    const unsigned sV0 = smB + OFF_V0 * 2, sP = smB + OFF_P * 2;

    const int tid = threadIdx.x, lane = tid & 31, wid = tid >> 5;
    const int tq = lane & 3, gq = lane >> 2;
    const int lr = lane & 15, lh = (lane >> 4) << 3;
    const int z = blockIdx.y, qt = blockIdx.x;

    const __half* Qp = Qg + (z * 1024 + qt * 128) * 64;
    const __half* Kp = Kg + z * 1024 * 64;
    const __half* Vp = Vg + z * 1024 * 64;

    auto stageT = [&](const __half* src, int kt, unsigned dst) {
#pragma unroll
        for (int i = 0; i < 4; i++) {
            const int c = tid + 256 * i;
            const int row = c >> 3, cc = (c & 7) * 8;
            cp16(dst + (row * QST + cc) * 2, src + (kt * 128 + row) * 64 + cc);
        }
    };

    // prologue: Q, K0, V0 + ones columns in both V buffers
#pragma unroll
    for (int i = 0; i < 4; i++) {
        const int c = tid + 256 * i;
        const int row = c >> 3, cc = (c & 7) * 8;
        cp16(sQ + (row * QST + cc) * 2, Qp + row * 64 + cc);
    }
    stageT(Kp, 0, sK);
    stageT(Vp, 0, sV0);
    {   // V padding cols 64..71: [1,0,0,0,0,0,0,0] per row, both buffers
        const int buf = tid >> 7, row = tid & 127;
        uint4 ones = make_uint4(0x00003C00u, 0u, 0u, 0u);
        *(uint4*)(sm + OFF_V0 + buf * VBUF + row * QST + 64) = ones;
    }
    cp_commit(); cp_wait0();
    __syncthreads();

    float oacc[9][4];
#pragma unroll
    for (int i = 0; i < 9; i++)
#pragma unroll
        for (int j = 0; j < 4; j++) oacc[i][j] = 0.f;
    float mrow0 = -1e30f, mrow1 = -1e30f;

    const unsigned aQbase = sQ + ((wid * 16 + lr) * QST + lh) * 2;
    const unsigned aPbase = sP + ((wid * 16 + lr) * PST + lh) * 2;
    // x4.trans V address component: lane -> (row-in-16, col-half)
    const int vrow = (lane & 7) + ((lane >> 3) & 1) * 8;
    const int vcol = (lane >> 4) << 3;

    for (int kt = 0; kt < 8; kt++) {
        const unsigned sV = sV0 + (kt & 1) * (VBUF * 2);

        // ---- S = Q @ K^T ----
        float sacc[16][4];
#pragma unroll
        for (int i = 0; i < 16; i++)
#pragma unroll
            for (int j = 0; j < 4; j++) sacc[i][j] = 0.f;
#pragma unroll
        for (int k16 = 0; k16 < 4; k16++) {
            const int kb = k16 * 32;
            unsigned a[4];
            ldm_x4(a[0], a[1], a[2], a[3], aQbase + kb);
#pragma unroll
            for (int ntp = 0; ntp < 8; ntp++) {
                unsigned t0, t1, t2, t3;
                ldm_x4(t0, t1, t2, t3, sK + ((ntp * 16 + lr) * QST) * 2 + lh * 2 + kb);
                unsigned b0[2] = { t0, t2 }, b1[2] = { t1, t3 };
                mma16(sacc[2 * ntp],     a, b0);
                mma16(sacc[2 * ntp + 1], a, b1);
            }
        }

        __syncthreads();
        if (kt < 7) {
            stageT(Kp, kt + 1, sK);
            stageT(Vp, kt + 1, sV0 + ((kt + 1) & 1) * (VBUF * 2));
            cp_commit();
        }

        // ---- online softmax (l via PV ones-column) ----
        float m0 = -1e30f, m1 = -1e30f;
#pragma unroll
        for (int nt = 0; nt < 16; nt++) {
            m0 = fmaxf(m0, fmaxf(sacc[nt][0], sacc[nt][1]));
            m1 = fmaxf(m1, fmaxf(sacc[nt][2], sacc[nt][3]));
        }
        m0 = fmaxf(m0, __shfl_xor_sync(0xffffffffu, m0, 1));
        m0 = fmaxf(m0, __shfl_xor_sync(0xffffffffu, m0, 2));
        m1 = fmaxf(m1, __shfl_xor_sync(0xffffffffu, m1, 1));
        m1 = fmaxf(m1, __shfl_xor_sync(0xffffffffu, m1, 2));
        const float mn0 = fmaxf(mrow0, m0), mn1 = fmaxf(mrow1, m1);
        const float sc0 = __expf(mrow0 - mn0), sc1 = __expf(mrow1 - mn1);
        mrow0 = mn0; mrow1 = mn1;

        const float L2E = 1.44269504f;
        const float nm0 = mn0 * L2E, nm1 = mn1 * L2E;
        const unsigned pAddr = sP + ((wid * 16 + lr) * PST) * 2;
#pragma unroll
        for (int nt = 0; nt < 16; nt++) {
            const float y0 = fmaf(sacc[nt][0], L2E, -nm0);
            const float y1 = fmaf(sacc[nt][1], L2E, -nm0);
            const float y2 = fmaf(sacc[nt][2], L2E, -nm1);
            const float y3 = fmaf(sacc[nt][3], L2E, -nm1);
            __half2 h01 = __floats2half2_rn(y0, y1);
            __half2 h23 = __floats2half2_rn(y2, y3);
            stm_x2(pAddr + nt * 16, ex2h2(*(unsigned*)&h01), ex2h2(*(unsigned*)&h23));
        }
#pragma unroll
        for (int nt = 0; nt < 9; nt++) {
            oacc[nt][0] *= sc0; oacc[nt][1] *= sc0;
            oacc[nt][2] *= sc1; oacc[nt][3] *= sc1;
        }
        __syncwarp();

        // ---- O(+l) += P @ [V | 1] ----
#pragma unroll
        for (int k16 = 0; k16 < 8; k16++) {
            const int k0 = k16 * 16;
            unsigned a[4];
            ldm_x4(a[0], a[1], a[2], a[3], aPbase + k16 * 32);
#pragma unroll
            for (int dk4 = 0; dk4 < 4; dk4++) {
                unsigned t0, t1, t2, t3;
                ldm_x4t(t0, t1, t2, t3,
                        sV + ((k0 + vrow) * QST + dk4 * 16 + vcol) * 2);
                unsigned b0[2] = { t0, t1 }, b1[2] = { t2, t3 };
                mma16(oacc[2 * dk4],     a, b0);
                mma16(oacc[2 * dk4 + 1], a, b1);
            }
            {   // l tile (cols 64..71 of V = [1,0,...])
                unsigned t0, t1;
                ldm_x2t(t0, t1, sV + ((k0 + lr) * QST + 64) * 2);
                unsigned b[2] = { t0, t1 };
                mma16(oacc[8], a, b);
            }
        }

        if (kt < 7) {
            cp_wait0();
            __syncthreads();
        }
    }

    // l lives in oacc[8] col 64 (tq==0 lanes); broadcast within quad
    const float l0 = __shfl_sync(0xffffffffu, oacc[8][0], lane & ~3);
    const float l1 = __shfl_sync(0xffffffffu, oacc[8][2], lane & ~3);
    const float i0 = 1.f / l0, i1 = 1.f / l1;
    const int b = z >> 4, h = z & 15;
    const int s0 = qt * 128 + wid * 16 + gq;
#pragma unroll
    for (int nt = 0; nt < 8; nt++) {
        const int col = h * 64 + nt * 8 + 2 * tq;
        *(__half2*)&O[(b * 1024 + s0) * 1024 + col] =
            __floats2half2_rn(oacc[nt][0] * i0, oacc[nt][1] * i0);
        *(__half2*)&O[(b * 1024 + s0 + 8) * 1024 + col] =
            __floats2half2_rn(oacc[nt][2] * i1, oacc[nt][3] * i1);
    }
}

// ---------------- out = x + LayerNorm(t)*g + b (+ fp16 copy) ----------------
__global__ void __launch_bounds__(256)
add_ln_kernel(const float* __restrict__ x, const float* __restrict__ t,
              const float* __restrict__ gw, const float* __restrict__ bw,
              float* __restrict__ out, __half* __restrict__ outh)
{
    __shared__ float r1[8], r2[8];
    const int base = blockIdx.x * 1024;
    const int tid = threadIdx.x;
    float4 tv = *(const float4*)(t + base + tid * 4);
    float s = tv.x + tv.y + tv.z + tv.w;
    float q = tv.x * tv.x + tv.y * tv.y + tv.z * tv.z + tv.w * tv.w;
#pragma unroll
    for (int o = 16; o; o >>= 1) {
        s += __shfl_xor_sync(0xffffffffu, s, o);
        q += __shfl_xor_sync(0xffffffffu, q, o);
    }
    if ((tid & 31) == 0) { r1[tid >> 5] = s; r2[tid >> 5] = q; }
    __syncthreads();
    if (tid < 32) {
        float ss = (tid < 8) ? r1[tid] : 0.f;
        float qq = (tid < 8) ? r2[tid] : 0.f;
#pragma unroll
        for (int o = 4; o; o >>= 1) {
            ss += __shfl_xor_sync(0xffffffffu, ss, o);
            qq += __shfl_xor_sync(0xffffffffu, qq, o);
        }
        if (tid == 0) { r1[0] = ss; r2[0] = qq; }
    }
    __syncthreads();
    const float mean = r1[0] * (1.f / 1024.f);
    const float var  = r2[0] * (1.f / 1024.f) - mean * mean;
    const float rstd = rsqrtf(var + 1e-5f);

    float4 xv = *(const float4*)(x + base + tid * 4);
    float4 gv = *(const float4*)(gw + tid * 4);
    float4 bv = *(const float4*)(bw + tid * 4);
    float4 o;
    o.x = xv.x + (tv.x - mean) * rstd * gv.x + bv.x;
    o.y = xv.y + (tv.y - mean) * rstd * gv.y + bv.y;
    o.z = xv.z + (tv.z - mean) * rstd * gv.z + bv.z;
    o.w = xv.w + (tv.w - mean) * rstd * gv.w + bv.w;
    *(float4*)(out + base + tid * 4) = o;
    if (outh) {
        __half2* oh = (__half2*)(outh + base + tid * 4);
        oh[0] = __floats2half2_rn(o.x, o.y);
        oh[1] = __floats2half2_rn(o.z, o.w);
    }
}

// ---------------- launch ----------------
template<class T>
static T* sym_addr(const void* s) {
    void* p = nullptr;
    cudaGetSymbolAddress(&p, s);
    return (T*)p;
}

extern "C" void kernel_launch(void* const* d_in, const int* in_sizes, int n_in,
                              void* d_out, int out_size)
{
    (void)in_sizes; (void)n_in; (void)out_size;
    const float* x   = (const float*)d_in[0];
    const float* Wq  = (const float*)d_in[1];
    const float* bq  = (const float*)d_in[2];
    const float* Wk  = (const float*)d_in[3];
    const float* bk  = (const float*)d_in[4];
    const float* Wv  = (const float*)d_in[5];
    const float* bv  = (const float*)d_in[6];
    const float* Wo  = (const float*)d_in[7];
    const float* bo  = (const float*)d_in[8];
    const float* W1  = (const float*)d_in[9];
    const float* b1  = (const float*)d_in[10];
    const float* W2  = (const float*)d_in[11];
    const float* b2  = (const float*)d_in[12];
    const float* g1  = (const float*)d_in[13];
    const float* be1 = (const float*)d_in[14];
    const float* g2  = (const float*)d_in[15];
    const float* be2 = (const float*)d_in[16];
    float* out = (float*)d_out;

    __half* xh   = sym_addr<__half>(g_xh);
    __half* wqkv = sym_addr<__half>(g_wqkv);
    __half* wo   = sym_addr<__half>(g_wo);
    __half* w1   = sym_addr<__half>(g_w1);
    __half* w2   = sym_addr<__half>(g_w2);
    __half* q    = sym_addr<__half>(g_q);
    __half* k    = sym_addr<__half>(g_k);
    __half* v    = sym_addr<__half>(g_v);
    __half* oc   = sym_addr<__half>(g_oc);
    float*  at   = sym_addr<float>(g_at);
    float*  x1   = sym_addr<float>(g_x1);
    __half* x1h  = sym_addr<__half>(g_x1h);
    __half* ff   = sym_addr<__half>(g_ff);
    float*  ps   = sym_addr<float>(g_ps);

    const int FSM = FL_SMH * 2;
    cudaFuncSetAttribute(gemm_h2<0>, cudaFuncAttributeMaxDynamicSharedMemorySize, G2SM);
    cudaFuncSetAttribute(gemm_h2<1>, cudaFuncAttributeMaxDynamicSharedMemorySize, G2SM);
    cudaFuncSetAttribute(gemm_h2<2>, cudaFuncAttributeMaxDynamicSharedMemorySize, G2SM);
    cudaFuncSetAttribute(flash_h,    cudaFuncAttributeMaxDynamicSharedMemorySize, FSM);

    const dim3 blk(256);

    cvt_all<<<16384, dim3(32, 8)>>>(x, Wq, Wk, Wv, Wo, W1, W2,
                                    xh, wqkv, wo, w1, w2);

    // fused QKV projection (q scaled by 1/8 in epilogue); all outputs [z][s][dk]
    gemm_h2<1><<<dim3(24, 32), blk, G2SM>>>(xh, wqkv, bq, bk, bv,
                                            q, k, v, 4096, 3072, 1024, 0);

    flash_h<<<dim3(8, 64), blk, FSM>>>(q, k, v, oc);

    gemm_h2<2><<<dim3(8, 32), blk, G2SM>>>(oc, wo, bo, nullptr, nullptr,
                                           at, nullptr, nullptr, 4096, 1024, 1024, 0);
    add_ln_kernel<<<4096, blk>>>(x, at, g1, be1, x1, x1h);

    gemm_h2<0><<<dim3(32, 32), blk, G2SM>>>(x1h, w1, b1, nullptr, nullptr,
                                            ff, nullptr, nullptr, 4096, 4096, 1024, 1);
    gemm_h2<2><<<dim3(8, 32), blk, G2SM>>>(ff, w2, b2, nullptr, nullptr,
                                           ps, nullptr, nullptr, 4096, 1024, 4096, 0);

    add_ln_kernel<<<4096, blk>>>(x1, ps, g2, be2, out, nullptr);
}

// round 8
// speedup vs baseline: 4.4232x; 1.1150x over previous
#include <cuda_runtime.h>
#include <cuda_fp16.h>

#define BB 4
#define SS 1024
#define DD 1024
#define HH 16
#define DKC 64
#define DFF 4096

// ---------------- scratch ----------------
__device__ __half g_xh  [BB*SS*DD];
__device__ __half g_wqkv[DD*3*DD];          // [k=1024 d][n=3072: seg*1024+h*64+dk]
__device__ __half g_wo  [DD*DD];            // [K,N]
__device__ __half g_w1  [DD*DFF];           // [1024,4096]
__device__ __half g_w2  [DFF*DD];           // [4096,1024]
__device__ __half g_q   [BB*HH*SS*DKC];     // [z][s][dk]
__device__ __half g_k   [BB*HH*SS*DKC];
__device__ __half g_v   [BB*HH*SS*DKC];
__device__ __half g_oc  [BB*SS*DD];
__device__ float  g_at  [BB*SS*DD];
__device__ float  g_x1  [BB*SS*DD];
__device__ __half g_x1h [BB*SS*DD];
__device__ __half g_ff  [BB*SS*DFF];
__device__ float  g_ps  [BB*SS*DD];

// ---------------- asm helpers ----------------
__device__ __forceinline__ void cp16(unsigned dst, const void* src) {
    asm volatile("cp.async.cg.shared.global [%0], [%1], 16;" :: "r"(dst), "l"(src));
}
__device__ __forceinline__ void cp_commit() { asm volatile("cp.async.commit_group;" ::: "memory"); }
__device__ __forceinline__ void cp_wait0()  { asm volatile("cp.async.wait_group 0;" ::: "memory"); }
__device__ __forceinline__ void cp_wait1()  { asm volatile("cp.async.wait_group 1;" ::: "memory"); }

__device__ __forceinline__ void ldm_x4(unsigned& r0, unsigned& r1, unsigned& r2, unsigned& r3, unsigned addr) {
    asm volatile("ldmatrix.sync.aligned.m8n8.x4.shared.b16 {%0,%1,%2,%3}, [%4];"
                 : "=r"(r0), "=r"(r1), "=r"(r2), "=r"(r3) : "r"(addr));
}
__device__ __forceinline__ void ldm_x4t(unsigned& r0, unsigned& r1, unsigned& r2, unsigned& r3, unsigned addr) {
    asm volatile("ldmatrix.sync.aligned.m8n8.x4.trans.shared.b16 {%0,%1,%2,%3}, [%4];"
                 : "=r"(r0), "=r"(r1), "=r"(r2), "=r"(r3) : "r"(addr));
}
__device__ __forceinline__ void ldm_x2t(unsigned& r0, unsigned& r1, unsigned addr) {
    asm volatile("ldmatrix.sync.aligned.m8n8.x2.trans.shared.b16 {%0,%1}, [%2];"
                 : "=r"(r0), "=r"(r1) : "r"(addr));
}
__device__ __forceinline__ void stm_x2(unsigned addr, unsigned r0, unsigned r1) {
    asm volatile("stmatrix.sync.aligned.m8n8.x2.shared.b16 [%0], {%1,%2};"
                 :: "r"(addr), "r"(r0), "r"(r1) : "memory");
}
__device__ __forceinline__ void mma16(float* c, const unsigned* a, const unsigned* b) {
    asm volatile(
        "mma.sync.aligned.m16n8k16.row.col.f32.f16.f16.f32 "
        "{%0,%1,%2,%3},{%4,%5,%6,%7},{%8,%9},{%0,%1,%2,%3};"
        : "+f"(c[0]), "+f"(c[1]), "+f"(c[2]), "+f"(c[3])
        : "r"(a[0]), "r"(a[1]), "r"(a[2]), "r"(a[3]), "r"(b[0]), "r"(b[1]));
}
__device__ __forceinline__ unsigned ex2h2(unsigned x) {
    unsigned r;
    asm("ex2.approx.f16x2 %0, %1;" : "=r"(r) : "r"(x));
    return r;
}

// ---------------- fused streaming conversion (no transposes) ----------------
// blocks [0,2048):      x -> xh (8 el/thread)
// blocks [2048,3584):   Wq/Wk/Wv [H,D,DK] -> wqkv [d][seg*1024+h*64+dk] (gather, coalesced)
// blocks [3584,4096):   Wo plain convert
// blocks [4096,6144):   W1 plain
// blocks [6144,8192):   W2 plain
__global__ void __launch_bounds__(256)
cvt_all(const float* __restrict__ x,
        const float* __restrict__ Wq, const float* __restrict__ Wk,
        const float* __restrict__ Wv, const float* __restrict__ Wo,
        const float* __restrict__ W1, const float* __restrict__ W2,
        __half* __restrict__ xh, __half* __restrict__ wqkv,
        __half* __restrict__ wo, __half* __restrict__ w1, __half* __restrict__ w2)
{
    const int tid = threadIdx.x;
    int b = blockIdx.x;

    if (b < 2048) {
        const int i = (b * 256 + tid) * 8;
        float4 v0 = *(const float4*)(x + i);
        float4 v1 = *(const float4*)(x + i + 4);
        __half2* o = (__half2*)(xh + i);
        o[0] = __floats2half2_rn(v0.x, v0.y);
        o[1] = __floats2half2_rn(v0.z, v0.w);
        o[2] = __floats2half2_rn(v1.x, v1.y);
        o[3] = __floats2half2_rn(v1.z, v1.w);
        return;
    }
    b -= 2048;
    if (b < 1536) {   // QKV pack: chunk of 8 halfs
        const int c = b * 256 + tid;                 // 0 .. 393215
        const int seg = c >> 17;
        const int r = c & 131071;
        const int d = r >> 7, h = (r >> 3) & 15, dk8 = r & 7;
        const float* src = (seg == 0 ? Wq : (seg == 1 ? Wk : Wv)) + h * 65536 + d * 64 + dk8 * 8;
        float4 a = *(const float4*)src;
        float4 bb = *(const float4*)(src + 4);
        __half2* o = (__half2*)(wqkv + d * 3072 + seg * 1024 + h * 64 + dk8 * 8);
        o[0] = __floats2half2_rn(a.x, a.y);
        o[1] = __floats2half2_rn(a.z, a.w);
        o[2] = __floats2half2_rn(bb.x, bb.y);
        o[3] = __floats2half2_rn(bb.z, bb.w);
        return;
    }
    b -= 1536;
    const float* src; __half* dst;
    if (b < 512)       { src = Wo; dst = wo; }
    else if (b < 2560) { b -= 512; src = W1; dst = w1; }
    else               { b -= 2560; src = W2; dst = w2; }
    const int i = (b * 256 + tid) * 8;
    float4 v0 = *(const float4*)(src + i);
    float4 v1 = *(const float4*)(src + i + 4);
    __half2* o = (__half2*)(dst + i);
    o[0] = __floats2half2_rn(v0.x, v0.y);
    o[1] = __floats2half2_rn(v0.z, v0.w);
    o[2] = __floats2half2_rn(v1.x, v1.y);
    o[3] = __floats2half2_rn(v1.z, v1.w);
}

// ---------------- fp16 GEMM: A[M,K] @ B[K,N], B staged [k][n] + x4t ----------------
#define STG_B 32768
#define G2SM  (3*STG_B)
// A tile swizzle (k-major rows of 128B)
__device__ __forceinline__ unsigned tswz(int row, int kbyte) {
    return (unsigned)(row * 128 + ((kbyte ^ ((row & 7) << 4)) & 127) + (kbyte & ~127));
}
// B tile swizzle (n-major rows of 256B): XOR 16B block by row&7 within each 128B half
__device__ __forceinline__ unsigned swz256(int row, int cb) {
    return (unsigned)(row * 256 + (cb & 128) + ((cb & 127) ^ ((row & 7) << 4)));
}

template<int EPI>
__global__ void __launch_bounds__(256, 2)
gemm_h2(const __half* __restrict__ A, const __half* __restrict__ B,
        const float* __restrict__ b0p, const float* __restrict__ b1p,
        const float* __restrict__ b2p, void* __restrict__ C0,
        void* __restrict__ C1, void* __restrict__ C2,
        int M, int N, int K, int relu)
{
    extern __shared__ char dsm[];
    const unsigned smB = (unsigned)__cvta_generic_to_shared(dsm);

    const int tid = threadIdx.x, lane = tid & 31, wid = tid >> 5;
    const int wm = wid & 1, wn = wid >> 1;
    const int Rb = blockIdx.y * 128;
    const int Nb = blockIdx.x * 128;
    const int nS = K >> 6;

    const int crow = tid >> 3, ckc = (tid & 7) * 16;   // A cp mapping
    const int lr = lane & 15, lhb = ((lane >> 4) << 4);
    const int vrow = (lane & 7) + ((lane >> 3) & 1) * 8;   // x4t lane mapping
    const int vcol = (lane >> 4) << 3;

    auto issue = [&](int it) {
        const unsigned sA = smB + (it % 3) * STG_B;
        const unsigned sB = sA + 16384;
        const __half* Ap = A + (Rb + crow) * K + it * 64 + ckc / 2;
#pragma unroll
        for (int i = 0; i < 4; i++)
            cp16(sA + tswz(crow + 32 * i, ckc), Ap + 32 * i * K);
#pragma unroll
        for (int i = 0; i < 4; i++) {
            const int c = tid + 256 * i;
            const int row = c >> 4, cb = (c & 15) * 16;
            cp16(sB + swz256(row, cb), B + (it * 64 + row) * N + Nb + (c & 15) * 8);
        }
    };

    float acc[4][4][4];
#pragma unroll
    for (int i = 0; i < 4; i++)
#pragma unroll
        for (int j = 0; j < 4; j++)
#pragma unroll
            for (int r = 0; r < 4; r++) acc[i][j][r] = 0.f;

    issue(0); cp_commit();
    issue(1); cp_commit();

    for (int it = 0; it < nS; it++) {
        cp_wait1();
        __syncthreads();
        if (it + 2 < nS) issue(it + 2);
        cp_commit();

        const unsigned sA = smB + (it % 3) * STG_B;
        const unsigned sB = sA + 16384;
#pragma unroll
        for (int s = 0; s < 4; s++) {
            const int kb = s * 32;          // A k byte offset
            const int ks = s * 16;          // B k row offset
            unsigned af[4][4], bf[2][4];
#pragma unroll
            for (int mt = 0; mt < 4; mt++)
                ldm_x4(af[mt][0], af[mt][1], af[mt][2], af[mt][3],
                       sA + tswz(wm * 64 + mt * 16 + lr, kb + lhb));
#pragma unroll
            for (int nt2 = 0; nt2 < 2; nt2++)
                ldm_x4t(bf[nt2][0], bf[nt2][1], bf[nt2][2], bf[nt2][3],
                        sB + swz256(ks + vrow, (wn * 32 + nt2 * 16 + vcol) * 2));
#pragma unroll
            for (int mt = 0; mt < 4; mt++)
#pragma unroll
                for (int nt = 0; nt < 4; nt++) {
                    unsigned b[2] = { bf[nt >> 1][(nt & 1) * 2], bf[nt >> 1][(nt & 1) * 2 + 1] };
                    mma16(acc[mt][nt], af[mt], b);
                }
        }
    }

    const int tq = lane & 3, gq = lane >> 2;

    if (EPI == 1) {
        __syncthreads();
        __half* ep = (__half*)dsm;
#pragma unroll
        for (int mt = 0; mt < 4; mt++) {
#pragma unroll
            for (int nt = 0; nt < 4; nt++) {
                const int n0 = Nb + wn * 32 + nt * 8 + tq * 2;
                const int seg = n0 >> 10, nn = n0 & 1023;
                const float* bp = seg == 0 ? b0p : (seg == 1 ? b1p : b2p);
                const int hh = nn >> 6, dk = nn & 63;
                const float bb0 = bp[hh * 64 + dk], bb1 = bp[hh * 64 + dk + 1];
                const float alpha = (seg == 0) ? 0.125f : 1.f;
#pragma unroll
                for (int half = 0; half < 2; half++) {
                    const int r = wm * 64 + mt * 16 + gq + half * 8;
                    float v0 = (acc[mt][nt][half * 2 + 0] + bb0) * alpha;
                    float v1 = (acc[mt][nt][half * 2 + 1] + bb1) * alpha;
                    *(__half2*)&ep[r * 136 + wn * 32 + nt * 8 + tq * 2] =
                        __floats2half2_rn(v0, v1);
                }
            }
        }
        __syncthreads();
        const int bidx = Rb >> 10, sbase = Rb & 1023;
        for (int c = tid; c < 2048; c += 256) {
            const int r = c >> 4, s16 = c & 15;
            uint4 val = *(uint4*)&ep[r * 136 + s16 * 8];
            const int n = Nb + s16 * 8;
            const int seg = n >> 10, nn = n & 1023;
            const int hh = nn >> 6, dk = nn & 63;
            __half* dst = seg == 0 ? (__half*)C0 : (seg == 1 ? (__half*)C1 : (__half*)C2);
            *(uint4*)&dst[(((bidx * 16 + hh) << 10) + sbase + r) * 64 + dk] = val;
        }
        return;
    }

#pragma unroll
    for (int mt = 0; mt < 4; mt++) {
#pragma unroll
        for (int nt = 0; nt < 4; nt++) {
            const int m0 = Rb + wm * 64 + mt * 16 + gq;
            const int n0 = Nb + wn * 32 + nt * 8 + tq * 2;
            const float bb0 = b0p ? b0p[n0] : 0.f;
            const float bb1 = b0p ? b0p[n0 + 1] : 0.f;
#pragma unroll
            for (int half = 0; half < 2; half++) {
                const int m = m0 + half * 8;
                float v0 = acc[mt][nt][half * 2 + 0] + bb0;
                float v1 = acc[mt][nt][half * 2 + 1] + bb1;
                if (relu) { v0 = fmaxf(v0, 0.f); v1 = fmaxf(v1, 0.f); }
                if (EPI == 0)
                    *(__half2*)((__half*)C0 + m * N + n0) = __floats2half2_rn(v0, v1);
                else
                    *(float2*)((float*)C0 + m * N + n0) = make_float2(v0, v1);
            }
        }
    }
}

// ---------------- fp16 flash attention v3 (unchanged from R7) ----------------
#define QST 72
#define PST 136
#define OFF_K  (128*QST)
#define OFF_V0 (2*128*QST)
#define VBUF   (128*QST)
#define OFF_P  (4*128*QST)
#define FL_SMH (OFF_P + 128*PST)
__global__ void __launch_bounds__(256, 2)
flash_h(const __half* __restrict__ Qg, const __half* __restrict__ Kg,
        const __half* __restrict__ Vg, __half* __restrict__ O)
{
    extern __shared__ __half sm[];
    const unsigned smB = (unsigned)__cvta_generic_to_shared(sm);
    const unsigned sQ = smB, sK = smB + OFF_K * 2;
    const unsigned sV0 = smB + OFF_V0 * 2, sP = smB + OFF_P * 2;

    const int tid = threadIdx.x, lane = tid & 31, wid = tid >> 5;
    const int tq = lane & 3, gq = lane >> 2;
    const int lr = lane & 15, lh = (lane >> 4) << 3;
    const int z = blockIdx.y, qt = blockIdx.x;

    const __half* Qp = Qg + (z * 1024 + qt * 128) * 64;
    const __half* Kp = Kg + z * 1024 * 64;
    const __half* Vp = Vg + z * 1024 * 64;

    auto stageT = [&](const __half* src, int kt, unsigned dst) {
#pragma unroll
        for (int i = 0; i < 4; i++) {
            const int c = tid + 256 * i;
            const int row = c >> 3, cc = (c & 7) * 8;
            cp16(dst + (row * QST + cc) * 2, src + (kt * 128 + row) * 64 + cc);
        }
    };

#pragma unroll
    for (int i = 0; i < 4; i++) {
        const int c = tid + 256 * i;
        const int row = c >> 3, cc = (c & 7) * 8;
        cp16(sQ + (row * QST + cc) * 2, Qp + row * 64 + cc);
    }
    stageT(Kp, 0, sK);
    stageT(Vp, 0, sV0);
    {
        const int buf = tid >> 7, row = tid & 127;
        uint4 ones = make_uint4(0x00003C00u, 0u, 0u, 0u);
        *(uint4*)(sm + OFF_V0 + buf * VBUF + row * QST + 64) = ones;
    }
    cp_commit(); cp_wait0();
    __syncthreads();

    float oacc[9][4];
#pragma unroll
    for (int i = 0; i < 9; i++)
#pragma unroll
        for (int j = 0; j < 4; j++) oacc[i][j] = 0.f;
    float mrow0 = -1e30f, mrow1 = -1e30f;

    const unsigned aQbase = sQ + ((wid * 16 + lr) * QST + lh) * 2;
    const unsigned aPbase = sP + ((wid * 16 + lr) * PST + lh) * 2;
    const int vrow = (lane & 7) + ((lane >> 3) & 1) * 8;
    const int vcol = (lane >> 4) << 3;

    for (int kt = 0; kt < 8; kt++) {
        const unsigned sV = sV0 + (kt & 1) * (VBUF * 2);

        float sacc[16][4];
#pragma unroll
        for (int i = 0; i < 16; i++)
#pragma unroll
            for (int j = 0; j < 4; j++) sacc[i][j] = 0.f;
#pragma unroll
        for (int k16 = 0; k16 < 4; k16++) {
            const int kb = k16 * 32;
            unsigned a[4];
            ldm_x4(a[0], a[1], a[2], a[3], aQbase + kb);
#pragma unroll
            for (int ntp = 0; ntp < 8; ntp++) {
                unsigned t0, t1, t2, t3;
                ldm_x4(t0, t1, t2, t3, sK + ((ntp * 16 + lr) * QST) * 2 + lh * 2 + kb);
                unsigned b0[2] = { t0, t2 }, b1[2] = { t1, t3 };
                mma16(sacc[2 * ntp],     a, b0);
                mma16(sacc[2 * ntp + 1], a, b1);
            }
        }

        __syncthreads();
        if (kt < 7) {
            stageT(Kp, kt + 1, sK);
            stageT(Vp, kt + 1, sV0 + ((kt + 1) & 1) * (VBUF * 2));
            cp_commit();
        }

        float m0 = -1e30f, m1 = -1e30f;
#pragma unroll
        for (int nt = 0; nt < 16; nt++) {
            m0 = fmaxf(m0, fmaxf(sacc[nt][0], sacc[nt][1]));
            m1 = fmaxf(m1, fmaxf(sacc[nt][2], sacc[nt][3]));
        }
        m0 = fmaxf(m0, __shfl_xor_sync(0xffffffffu, m0, 1));
        m0 = fmaxf(m0, __shfl_xor_sync(0xffffffffu, m0, 2));
        m1 = fmaxf(m1, __shfl_xor_sync(0xffffffffu, m1, 1));
        m1 = fmaxf(m1, __shfl_xor_sync(0xffffffffu, m1, 2));
        const float mn0 = fmaxf(mrow0, m0), mn1 = fmaxf(mrow1, m1);
        const float sc0 = __expf(mrow0 - mn0), sc1 = __expf(mrow1 - mn1);
        mrow0 = mn0; mrow1 = mn1;

        const float L2E = 1.44269504f;
        const float nm0 = mn0 * L2E, nm1 = mn1 * L2E;
        const unsigned pAddr = sP + ((wid * 16 + lr) * PST) * 2;
#pragma unroll
        for (int nt = 0; nt < 16; nt++) {
            const float y0 = fmaf(sacc[nt][0], L2E, -nm0);
            const float y1 = fmaf(sacc[nt][1], L2E, -nm0);
            const float y2 = fmaf(sacc[nt][2], L2E, -nm1);
            const float y3 = fmaf(sacc[nt][3], L2E, -nm1);
            __half2 h01 = __floats2half2_rn(y0, y1);
            __half2 h23 = __floats2half2_rn(y2, y3);
            stm_x2(pAddr + nt * 16, ex2h2(*(unsigned*)&h01), ex2h2(*(unsigned*)&h23));
        }
#pragma unroll
        for (int nt = 0; nt < 9; nt++) {
            oacc[nt][0] *= sc0; oacc[nt][1] *= sc0;
            oacc[nt][2] *= sc1; oacc[nt][3] *= sc1;
        }
        __syncwarp();

#pragma unroll
        for (int k16 = 0; k16 < 8; k16++) {
            const int k0 = k16 * 16;
            unsigned a[4];
            ldm_x4(a[0], a[1], a[2], a[3], aPbase + k16 * 32);
#pragma unroll
            for (int dk4 = 0; dk4 < 4; dk4++) {
                unsigned t0, t1, t2, t3;
                ldm_x4t(t0, t1, t2, t3,
                        sV + ((k0 + vrow) * QST + dk4 * 16 + vcol) * 2);
                unsigned b0[2] = { t0, t1 }, b1[2] = { t2, t3 };
                mma16(oacc[2 * dk4],     a, b0);
                mma16(oacc[2 * dk4 + 1], a, b1);
            }
            {
                unsigned t0, t1;
                ldm_x2t(t0, t1, sV + ((k0 + lr) * QST + 64) * 2);
                unsigned b[2] = { t0, t1 };
                mma16(oacc[8], a, b);
            }
        }

        if (kt < 7) {
            cp_wait0();
            __syncthreads();
        }
    }

    const float l0 = __shfl_sync(0xffffffffu, oacc[8][0], lane & ~3);
    const float l1 = __shfl_sync(0xffffffffu, oacc[8][2], lane & ~3);
    const float i0 = 1.f / l0, i1 = 1.f / l1;
    const int b = z >> 4, h = z & 15;
    const int s0 = qt * 128 + wid * 16 + gq;
#pragma unroll
    for (int nt = 0; nt < 8; nt++) {
        const int col = h * 64 + nt * 8 + 2 * tq;
        *(__half2*)&O[(b * 1024 + s0) * 1024 + col] =
            __floats2half2_rn(oacc[nt][0] * i0, oacc[nt][1] * i0);
        *(__half2*)&O[(b * 1024 + s0 + 8) * 1024 + col] =
            __floats2half2_rn(oacc[nt][2] * i1, oacc[nt][3] * i1);
    }
}

// ---------------- out = x + LayerNorm(t)*g + b (+ fp16 copy) ----------------
__global__ void __launch_bounds__(256)
add_ln_kernel(const float* __restrict__ x, const float* __restrict__ t,
              const float* __restrict__ gw, const float* __restrict__ bw,
              float* __restrict__ out, __half* __restrict__ outh)
{
    __shared__ float r1[8], r2[8];
    const int base = blockIdx.x * 1024;
    const int tid = threadIdx.x;
    float4 tv = *(const float4*)(t + base + tid * 4);
    float s = tv.x + tv.y + tv.z + tv.w;
    float q = tv.x * tv.x + tv.y * tv.y + tv.z * tv.z + tv.w * tv.w;
#pragma unroll
    for (int o = 16; o; o >>= 1) {
        s += __shfl_xor_sync(0xffffffffu, s, o);
        q += __shfl_xor_sync(0xffffffffu, q, o);
    }
    if ((tid & 31) == 0) { r1[tid >> 5] = s; r2[tid >> 5] = q; }
    __syncthreads();
    if (tid < 32) {
        float ss = (tid < 8) ? r1[tid] : 0.f;
        float qq = (tid < 8) ? r2[tid] : 0.f;
#pragma unroll
        for (int o = 4; o; o >>= 1) {
            ss += __shfl_xor_sync(0xffffffffu, ss, o);
            qq += __shfl_xor_sync(0xffffffffu, qq, o);
        }
        if (tid == 0) { r1[0] = ss; r2[0] = qq; }
    }
    __syncthreads();
    const float mean = r1[0] * (1.f / 1024.f);
    const float var  = r2[0] * (1.f / 1024.f) - mean * mean;
    const float rstd = rsqrtf(var + 1e-5f);

    float4 xv = *(const float4*)(x + base + tid * 4);
    float4 gv = *(const float4*)(gw + tid * 4);
    float4 bv = *(const float4*)(bw + tid * 4);
    float4 o;
    o.x = xv.x + (tv.x - mean) * rstd * gv.x + bv.x;
    o.y = xv.y + (tv.y - mean) * rstd * gv.y + bv.y;
    o.z = xv.z + (tv.z - mean) * rstd * gv.z + bv.z;
    o.w = xv.w + (tv.w - mean) * rstd * gv.w + bv.w;
    *(float4*)(out + base + tid * 4) = o;
    if (outh) {
        __half2* oh = (__half2*)(outh + base + tid * 4);
        oh[0] = __floats2half2_rn(o.x, o.y);
        oh[1] = __floats2half2_rn(o.z, o.w);
    }
}

// ---------------- launch ----------------
template<class T>
static T* sym_addr(const void* s) {
    void* p = nullptr;
    cudaGetSymbolAddress(&p, s);
    return (T*)p;
}

extern "C" void kernel_launch(void* const* d_in, const int* in_sizes, int n_in,
                              void* d_out, int out_size)
{
    (void)in_sizes; (void)n_in; (void)out_size;
    const float* x   = (const float*)d_in[0];
    const float* Wq  = (const float*)d_in[1];
    const float* bq  = (const float*)d_in[2];
    const float* Wk  = (const float*)d_in[3];
    const float* bk  = (const float*)d_in[4];
    const float* Wv  = (const float*)d_in[5];
    const float* bv  = (const float*)d_in[6];
    const float* Wo  = (const float*)d_in[7];
    const float* bo  = (const float*)d_in[8];
    const float* W1  = (const float*)d_in[9];
    const float* b1  = (const float*)d_in[10];
    const float* W2  = (const float*)d_in[11];
    const float* b2  = (const float*)d_in[12];
    const float* g1  = (const float*)d_in[13];
    const float* be1 = (const float*)d_in[14];
    const float* g2  = (const float*)d_in[15];
    const float* be2 = (const float*)d_in[16];
    float* out = (float*)d_out;

    __half* xh   = sym_addr<__half>(g_xh);
    __half* wqkv = sym_addr<__half>(g_wqkv);
    __half* wo   = sym_addr<__half>(g_wo);
    __half* w1   = sym_addr<__half>(g_w1);
    __half* w2   = sym_addr<__half>(g_w2);
    __half* q    = sym_addr<__half>(g_q);
    __half* k    = sym_addr<__half>(g_k);
    __half* v    = sym_addr<__half>(g_v);
    __half* oc   = sym_addr<__half>(g_oc);
    float*  at   = sym_addr<float>(g_at);
    float*  x1   = sym_addr<float>(g_x1);
    __half* x1h  = sym_addr<__half>(g_x1h);
    __half* ff   = sym_addr<__half>(g_ff);
    float*  ps   = sym_addr<float>(g_ps);

    const int FSM = FL_SMH * 2;
    cudaFuncSetAttribute(gemm_h2<0>, cudaFuncAttributeMaxDynamicSharedMemorySize, G2SM);
    cudaFuncSetAttribute(gemm_h2<1>, cudaFuncAttributeMaxDynamicSharedMemorySize, G2SM);
    cudaFuncSetAttribute(gemm_h2<2>, cudaFuncAttributeMaxDynamicSharedMemorySize, G2SM);
    cudaFuncSetAttribute(flash_h,    cudaFuncAttributeMaxDynamicSharedMemorySize, FSM);

    const dim3 blk(256);

    cvt_all<<<8192, blk>>>(x, Wq, Wk, Wv, Wo, W1, W2,
                           xh, wqkv, wo, w1, w2);

    // fused QKV projection (q scaled by 1/8 in epilogue)
    gemm_h2<1><<<dim3(24, 32), blk, G2SM>>>(xh, wqkv, bq, bk, bv,
                                            q, k, v, 4096, 3072, 1024, 0);

    flash_h<<<dim3(8, 64), blk, FSM>>>(q, k, v, oc);

    gemm_h2<2><<<dim3(8, 32), blk, G2SM>>>(oc, wo, bo, nullptr, nullptr,
                                           at, nullptr, nullptr, 4096, 1024, 1024, 0);
    add_ln_kernel<<<4096, blk>>>(x, at, g1, be1, x1, x1h);

    gemm_h2<0><<<dim3(32, 32), blk, G2SM>>>(x1h, w1, b1, nullptr, nullptr,
                                            ff, nullptr, nullptr, 4096, 4096, 1024, 1);
    gemm_h2<2><<<dim3(8, 32), blk, G2SM>>>(ff, w2, b2, nullptr, nullptr,
                                           ps, nullptr, nullptr, 4096, 1024, 4096, 0);

    add_ln_kernel<<<4096, blk>>>(x1, ps, g2, be2, out, nullptr);
}